// round 5
// baseline (speedup 1.0000x reference)
#include <cuda_runtime.h>
#include <cuda_bf16.h>

// fastmax attention, B=1, H=8, N=2048, D=64, causal, with RPE.
// s[i,j] = q_i . (k_j + rpe[i-j+N-1]);  w = 1 + s + s^2/2 (j<=i else 0)
// out[i] = (sum_j w*v_j) / (sum_j w)
//
// One block = i-tile pair (t, 31-t) for one head -> 33 j-tile units per block,
// perfectly balanced. Grid (16, 8) = 128 blocks.

#define NSEQ 2048
#define DIM  64
#define TI   64
#define TJ   64
#define WS   68            // sW row stride in floats (bank-conflict pad)
#define NTILES 32          // NSEQ / TI

// smem (float4 units): sQ 1024, sK 1024, sV 1024, sR 2048, then sW 64*68 floats
#define SMEM_BYTES ((1024 + 1024 + 1024 + 2048) * 16 + 64 * WS * 4)

// XOR swizzle within a 64-row tile: float4 index for [row][c], c in 0..15.
// Guarantees conflict-free LDS.128 when a warp reads the same c across rows
// distinct mod 16 (our strided phase-A mapping), and across c for fixed row.
__device__ __forceinline__ int sw(int row, int c) {
    return row * 16 + (c ^ (row & 15));
}

__global__ __launch_bounds__(256)
void fastmax_kernel(const float* __restrict__ q,
                    const float* __restrict__ k,
                    const float* __restrict__ v,
                    const float* __restrict__ rpe,
                    float* __restrict__ out)
{
    extern __shared__ float smem[];
    float4* sQ = reinterpret_cast<float4*>(smem);          // 64 x 16 f4, swizzled
    float4* sK = sQ + 1024;                                // 64 x 16 f4, swizzled
    float4* sV = sK + 1024;                                // 64 x 16 f4, plain
    float4* sR = sV + 1024;                                // 128 x 16 f4, swizzled
    float*  sW = reinterpret_cast<float*>(sR + 2048);      // [j][i] transposed, stride WS

    const int h   = blockIdx.y;
    const int tid = threadIdx.x;
    const int ti  = tid >> 4;      // 0..15
    const int tj  = tid & 15;      // 0..15

    const float4* gq = reinterpret_cast<const float4*>(q + (size_t)h * NSEQ * DIM);
    const float4* gk = reinterpret_cast<const float4*>(k + (size_t)h * NSEQ * DIM);
    const float4* gv = reinterpret_cast<const float4*>(v + (size_t)h * NSEQ * DIM);
    const float4* gr = reinterpret_cast<const float4*>(rpe);
    float4* gout     = reinterpret_cast<float4*>(out + (size_t)h * NSEQ * DIM);

    for (int half = 0; half < 2; half++) {
        const int itile = (half == 0) ? (int)blockIdx.x : (NTILES - 1 - (int)blockIdx.x);
        const int i0 = itile * TI;

        __syncthreads();
        // ---- load Q tile (swizzled) ----
        #pragma unroll
        for (int it = 0; it < 4; it++) {
            int idx = tid + it * 256;
            int row = idx >> 4, c = idx & 15;
            sQ[sw(row, c)] = gq[(i0 + row) * 16 + c];
        }

        // per-thread output accumulators for phase B rows i0 + 4*ti + a
        float4 o0 = make_float4(0.f, 0.f, 0.f, 0.f);
        float4 o1 = o0, o2 = o0, o3 = o0;
        float  d0 = 0.f, d1 = 0.f, d2 = 0.f, d3 = 0.f;

        const int njt = itile + 1;
        for (int jt = 0; jt < njt; jt++) {
            const int j0 = jt * TJ;

            __syncthreads();   // previous phase B done; Q fill visible

            // ---- fill K (swizzled), V (plain) ----
            #pragma unroll
            for (int it = 0; it < 4; it++) {
                int idx = tid + it * 256;
                int row = idx >> 4, c = idx & 15;
                float4 kv4 = gk[(j0 + row) * 16 + c];
                float4 vv4 = gv[(j0 + row) * 16 + c];
                sK[sw(row, c)] = kv4;
                sV[row * 16 + c] = vv4;
            }
            // ---- fill RPE band: local row li holds global rel = rmin + li ----
            // rel(i,j) = (i - j) + N - 1;  li = (i_r - j_c) + (TJ-1);  rmin = i0-j0+N-TJ
            const int rmin = i0 - j0 + (NSEQ - TJ);
            #pragma unroll
            for (int it = 0; it < 8; it++) {
                int idx = tid + it * 256;
                int row = idx >> 4, c = idx & 15;
                int rr  = rmin + (row < 127 ? row : 126);   // row 127 is pad
                sR[sw(row, c)] = gr[rr * 16 + c];
            }
            __syncthreads();

            // ---- phase A: W tile. thread -> rows i_r = ti+16a, cols j_c = tj+16b ----
            float acc[4][4];
            #pragma unroll
            for (int a = 0; a < 4; a++)
                #pragma unroll
                for (int b = 0; b < 4; b++) acc[a][b] = 0.f;

            const int rbase = ti - tj + (TJ - 1);   // in [48, 78]
            #pragma unroll 2
            for (int dg = 0; dg < 16; dg++) {
                float4 qv[4], kv[4], rv[7];
                #pragma unroll
                for (int a = 0; a < 4; a++) qv[a] = sQ[sw(ti + 16 * a, dg)];
                #pragma unroll
                for (int b = 0; b < 4; b++) kv[b] = sK[sw(tj + 16 * b, dg)];
                #pragma unroll
                for (int t = 0; t < 7; t++) rv[t] = sR[sw(rbase + 16 * (t - 3), dg)];
                #pragma unroll
                for (int a = 0; a < 4; a++) {
                    #pragma unroll
                    for (int b = 0; b < 4; b++) {
                        const float4 rr = rv[a - b + 3];   // li = rbase + 16*(a-b)
                        acc[a][b] += qv[a].x * (kv[b].x + rr.x)
                                   + qv[a].y * (kv[b].y + rr.y)
                                   + qv[a].z * (kv[b].z + rr.z)
                                   + qv[a].w * (kv[b].w + rr.w);
                    }
                }
            }

            // weight + causal mask + store transposed
            #pragma unroll
            for (int a = 0; a < 4; a++) {
                const int gi = i0 + ti + 16 * a;
                #pragma unroll
                for (int b = 0; b < 4; b++) {
                    const int gj = j0 + tj + 16 * b;
                    float s = acc[a][b];
                    float w = 1.0f + s + 0.5f * s * s;
                    if (gj > gi) w = 0.0f;
                    sW[(tj + 16 * b) * WS + (ti + 16 * a)] = w;
                }
            }
            __syncthreads();

            // ---- phase B: out += W * V ; rows i_r = 4*ti + a, dcols = 4*tj + b ----
            #pragma unroll 8
            for (int j = 0; j < TJ; j++) {
                const float4 w4 = *reinterpret_cast<const float4*>(&sW[j * WS + 4 * ti]);
                const float4 v4 = sV[j * 16 + tj];
                o0.x += w4.x * v4.x; o0.y += w4.x * v4.y; o0.z += w4.x * v4.z; o0.w += w4.x * v4.w;
                o1.x += w4.y * v4.x; o1.y += w4.y * v4.y; o1.z += w4.y * v4.z; o1.w += w4.y * v4.w;
                o2.x += w4.z * v4.x; o2.y += w4.z * v4.y; o2.z += w4.z * v4.z; o2.w += w4.z * v4.w;
                o3.x += w4.w * v4.x; o3.y += w4.w * v4.y; o3.z += w4.w * v4.z; o3.w += w4.w * v4.w;
                d0 += w4.x; d1 += w4.y; d2 += w4.z; d3 += w4.w;
            }
        }

        // ---- epilogue: normalize + write. rows i0 + 4*ti + a, f4 col tj ----
        {
            const float i0f = 1.0f / d0, i1f = 1.0f / d1, i2f = 1.0f / d2, i3f = 1.0f / d3;
            float4 r;
            r.x = o0.x * i0f; r.y = o0.y * i0f; r.z = o0.z * i0f; r.w = o0.w * i0f;
            gout[(i0 + 4 * ti + 0) * 16 + tj] = r;
            r.x = o1.x * i1f; r.y = o1.y * i1f; r.z = o1.z * i1f; r.w = o1.w * i1f;
            gout[(i0 + 4 * ti + 1) * 16 + tj] = r;
            r.x = o2.x * i2f; r.y = o2.y * i2f; r.z = o2.z * i2f; r.w = o2.w * i2f;
            gout[(i0 + 4 * ti + 2) * 16 + tj] = r;
            r.x = o3.x * i3f; r.y = o3.y * i3f; r.z = o3.z * i3f; r.w = o3.w * i3f;
            gout[(i0 + 4 * ti + 3) * 16 + tj] = r;
        }
    }
}

extern "C" void kernel_launch(void* const* d_in, const int* in_sizes, int n_in,
                              void* d_out, int out_size)
{
    (void)in_sizes; (void)n_in; (void)out_size;
    const float* q   = (const float*)d_in[0];
    const float* k   = (const float*)d_in[1];
    const float* v   = (const float*)d_in[2];
    const float* rpe = (const float*)d_in[3];
    // d_in[4] = mask scalar: reference always uses causal (mask=1); baked in.
    float* out = (float*)d_out;

    cudaFuncSetAttribute(fastmax_kernel,
                         cudaFuncAttributeMaxDynamicSharedMemorySize, SMEM_BYTES);
    fastmax_kernel<<<dim3(16, 8), 256, SMEM_BYTES>>>(q, k, v, rpe, out);
}

// round 6
// speedup vs baseline: 1.2006x; 1.2006x over previous
#include <cuda_runtime.h>
#include <cuda_bf16.h>

// fastmax attention, B=1, H=8, N=2048, D=64, causal, with RPE.
// s[i,j] = q_i . (k_j + rpe[i-j+N-1]);  w = 1 + s + s^2/2 (j<=i else 0)
// out[i] = (sum_j w*v_j) / (sum_j w)
//
// One block = i-tile pair (t, 31-t) for one head -> 33 j-tile units per block.
// Grid (16, 8) = 128 blocks. Inner math uses packed f32x2 (FFMA2 path).

#define NSEQ 2048
#define DIM  64
#define TI   64
#define TJ   64
#define NTILES 32

typedef unsigned long long u64;

// smem (floats): sQ 64x16f4, sK 64x16f4, sVd 64x32f4 (duplicated V),
// sR 128x16f4, sW 64x64 floats (XOR-swizzled)
#define SMEM_BYTES ((1024 + 1024 + 2048 + 2048) * 16 + 4096 * 4)

__device__ __forceinline__ u64 fma2(u64 a, u64 b, u64 c) {
    u64 d; asm("fma.rn.f32x2 %0, %1, %2, %3;" : "=l"(d) : "l"(a), "l"(b), "l"(c)); return d;
}
__device__ __forceinline__ u64 add2(u64 a, u64 b) {
    u64 d; asm("add.rn.f32x2 %0, %1, %2;" : "=l"(d) : "l"(a), "l"(b)); return d;
}
__device__ __forceinline__ float2 unpack2(u64 x) {
    float lo, hi; asm("mov.b64 {%0, %1}, %2;" : "=f"(lo), "=f"(hi) : "l"(x));
    return make_float2(lo, hi);
}

// XOR swizzle, float4 index for [row][c], c in 0..15 (conflict-free for
// distinct-mod-16 row access patterns).
__device__ __forceinline__ int sw(int row, int c) { return row * 16 + (c ^ (row & 15)); }

__global__ __launch_bounds__(256)
void fastmax_kernel(const float* __restrict__ q,
                    const float* __restrict__ k,
                    const float* __restrict__ v,
                    const float* __restrict__ rpe,
                    float* __restrict__ out)
{
    extern __shared__ float smem[];
    float4* sQ  = reinterpret_cast<float4*>(smem);     // 1024 f4, swizzled
    float4* sK  = sQ + 1024;                           // 1024 f4, swizzled
    float4* sVd = sK + 1024;                           // 2048 f4, duplicated pairs
    float4* sR  = sVd + 2048;                          // 2048 f4, swizzled
    float*  sW  = reinterpret_cast<float*>(sR + 2048); // 64*64, XOR-by-j swizzle

    const int h   = blockIdx.y;
    const int tid = threadIdx.x;
    const int ti  = tid >> 4;      // 0..15
    const int tj  = tid & 15;      // 0..15

    const float4* gq = reinterpret_cast<const float4*>(q + (size_t)h * NSEQ * DIM);
    const float4* gk = reinterpret_cast<const float4*>(k + (size_t)h * NSEQ * DIM);
    const float4* gv = reinterpret_cast<const float4*>(v + (size_t)h * NSEQ * DIM);
    const float4* gr = reinterpret_cast<const float4*>(rpe);
    float4* gout     = reinterpret_cast<float4*>(out + (size_t)h * NSEQ * DIM);

    for (int half = 0; half < 2; half++) {
        const int itile = (half == 0) ? (int)blockIdx.x : (NTILES - 1 - (int)blockIdx.x);
        const int i0 = itile * TI;

        __syncthreads();   // previous half's phase B fully done before sQ overwrite
        // ---- load Q tile (swizzled) ----
        #pragma unroll
        for (int it = 0; it < 4; it++) {
            int idx = tid + it * 256;
            int row = idx >> 4, c = idx & 15;
            sQ[sw(row, c)] = gq[(i0 + row) * 16 + c];
        }

        // phase-B accumulators: o[rp][c] packs rows (4ti+2rp, 4ti+2rp+1), col 4tj+c
        u64 o00 = 0, o01 = 0, o02 = 0, o03 = 0;
        u64 o10 = 0, o11 = 0, o12 = 0, o13 = 0;
        u64 dac0 = 0, dac1 = 0;

        const int njt = itile + 1;
        for (int jt = 0; jt < njt; jt++) {
            const int j0 = jt * TJ;

            __syncthreads();   // previous phase B done; Q fill visible

            // ---- fill K (swizzled) and duplicated V ----
            #pragma unroll
            for (int it = 0; it < 4; it++) {
                int idx = tid + it * 256;
                int row = idx >> 4, c = idx & 15;
                float4 kv4 = gk[(j0 + row) * 16 + c];
                float4 vv4 = gv[(j0 + row) * 16 + c];
                sK[sw(row, c)] = kv4;
                sVd[row * 32 + 2 * c]     = make_float4(vv4.x, vv4.x, vv4.y, vv4.y);
                sVd[row * 32 + 2 * c + 1] = make_float4(vv4.z, vv4.z, vv4.w, vv4.w);
            }
            // ---- fill RPE band: local row li holds rel = rmin + li ----
            const int rmin = i0 - j0 + (NSEQ - TJ);
            #pragma unroll
            for (int it = 0; it < 8; it++) {
                int idx = tid + it * 256;
                int row = idx >> 4, c = idx & 15;
                int rr  = rmin + (row < 127 ? row : 126);   // row 127 is pad
                sR[sw(row, c)] = gr[rr * 16 + c];
            }
            __syncthreads();

            // ---- phase A: packed f32x2 score accumulation ----
            u64 acc[4][4];
            #pragma unroll
            for (int a = 0; a < 4; a++)
                #pragma unroll
                for (int b = 0; b < 4; b++) acc[a][b] = 0ull;

            const int rbase = ti - tj + (TJ - 1);   // in [48, 78]
            #pragma unroll 2
            for (int dg = 0; dg < 16; dg++) {
                ulonglong2 qv[4], kv[4], rv[7];
                #pragma unroll
                for (int a = 0; a < 4; a++)
                    qv[a] = *reinterpret_cast<const ulonglong2*>(&sQ[sw(ti + 16 * a, dg)]);
                #pragma unroll
                for (int b = 0; b < 4; b++)
                    kv[b] = *reinterpret_cast<const ulonglong2*>(&sK[sw(tj + 16 * b, dg)]);
                #pragma unroll
                for (int t = 0; t < 7; t++)
                    rv[t] = *reinterpret_cast<const ulonglong2*>(&sR[sw(rbase + 16 * (t - 3), dg)]);
                #pragma unroll
                for (int a = 0; a < 4; a++) {
                    #pragma unroll
                    for (int b = 0; b < 4; b++) {
                        const ulonglong2 rr = rv[a - b + 3];
                        u64 t0 = add2(kv[b].x, rr.x);
                        u64 t1 = add2(kv[b].y, rr.y);
                        acc[a][b] = fma2(qv[a].x, t0, acc[a][b]);
                        acc[a][b] = fma2(qv[a].y, t1, acc[a][b]);
                    }
                }
            }

            // ---- weight + causal mask, store to sW (XOR-by-j swizzle) ----
            {
                const int i4b = ti >> 2, ilo = ti & 3;
                #pragma unroll
                for (int a = 0; a < 4; a++) {
                    const int gi = i0 + ti + 16 * a;
                    const int i4 = i4b + 4 * a;
                    #pragma unroll
                    for (int b = 0; b < 4; b++) {
                        const int gj = j0 + tj + 16 * b;
                        float2 p = unpack2(acc[a][b]);
                        float s = p.x + p.y;
                        float w = fmaf(0.5f * s, s, 1.0f + s);
                        if (gj > gi) w = 0.0f;
                        sW[(tj + 16 * b) * 64 + (((i4 ^ tj) << 2) | ilo)] = w;
                    }
                }
            }
            __syncthreads();

            // ---- phase B: out += W * V (packed row-pairs x broadcast-V) ----
            const ulonglong2* vd = reinterpret_cast<const ulonglong2*>(sVd);
            #pragma unroll 8
            for (int j = 0; j < TJ; j++) {
                const ulonglong2 wv = *reinterpret_cast<const ulonglong2*>(
                    &sW[j * 64 + ((ti ^ (j & 15)) << 2)]);   // (w0,w1),(w2,w3)
                const ulonglong2 va = vd[j * 32 + 2 * tj];       // (v0,v0),(v1,v1)
                const ulonglong2 vb = vd[j * 32 + 2 * tj + 1];   // (v2,v2),(v3,v3)
                o00 = fma2(wv.x, va.x, o00);
                o01 = fma2(wv.x, va.y, o01);
                o02 = fma2(wv.x, vb.x, o02);
                o03 = fma2(wv.x, vb.y, o03);
                o10 = fma2(wv.y, va.x, o10);
                o11 = fma2(wv.y, va.y, o11);
                o12 = fma2(wv.y, vb.x, o12);
                o13 = fma2(wv.y, vb.y, o13);
                dac0 = add2(dac0, wv.x);
                dac1 = add2(dac1, wv.y);
            }
        }

        // ---- epilogue: normalize + write rows i0 + 4*ti + r, f4 col tj ----
        {
            float2 dlo = unpack2(dac0), dhi = unpack2(dac1);
            float2 c0l = unpack2(o00), c1l = unpack2(o01), c2l = unpack2(o02), c3l = unpack2(o03);
            float2 c0h = unpack2(o10), c1h = unpack2(o11), c2h = unpack2(o12), c3h = unpack2(o13);
            float inv; float4 r;

            inv = 1.0f / dlo.x;
            r = make_float4(c0l.x * inv, c1l.x * inv, c2l.x * inv, c3l.x * inv);
            gout[(i0 + 4 * ti + 0) * 16 + tj] = r;
            inv = 1.0f / dlo.y;
            r = make_float4(c0l.y * inv, c1l.y * inv, c2l.y * inv, c3l.y * inv);
            gout[(i0 + 4 * ti + 1) * 16 + tj] = r;
            inv = 1.0f / dhi.x;
            r = make_float4(c0h.x * inv, c1h.x * inv, c2h.x * inv, c3h.x * inv);
            gout[(i0 + 4 * ti + 2) * 16 + tj] = r;
            inv = 1.0f / dhi.y;
            r = make_float4(c0h.y * inv, c1h.y * inv, c2h.y * inv, c3h.y * inv);
            gout[(i0 + 4 * ti + 3) * 16 + tj] = r;
        }
    }
}

extern "C" void kernel_launch(void* const* d_in, const int* in_sizes, int n_in,
                              void* d_out, int out_size)
{
    (void)in_sizes; (void)n_in; (void)out_size;
    const float* q   = (const float*)d_in[0];
    const float* k   = (const float*)d_in[1];
    const float* v   = (const float*)d_in[2];
    const float* rpe = (const float*)d_in[3];
    float* out = (float*)d_out;

    cudaFuncSetAttribute(fastmax_kernel,
                         cudaFuncAttributeMaxDynamicSharedMemorySize, SMEM_BYTES);
    fastmax_kernel<<<dim3(16, 8), 256, SMEM_BYTES>>>(q, k, v, rpe, out);
}

// round 7
// speedup vs baseline: 1.5474x; 1.2888x over previous
#include <cuda_runtime.h>
#include <cuda_bf16.h>

// fastmax attention, B=1, H=8, N=2048, D=64, causal, with RPE.
// s[i,j] = q_i . (k_j + rpe[i-j+N-1]);  w = 1 + s + s^2/2 (j<=i else 0)
// out[i] = (sum_j w*v_j) / (sum_j w)
//
// One block = i-tile pair (t, 31-t) for one head -> 33 j-tile units per block.
// Grid (16, 8) = 128 blocks. Packed f32x2 math (FFMA2).
// Warp footprint = 8 ti x 4 tj to minimize distinct smem rows per warp
// (rv: 11 distinct vs 17; phase-B vd: 4 distinct vs 16).
// RPE band kept in a 128-row circular buffer: only 64 new rows per j-tile.

#define NSEQ 2048
#define DIM  64
#define TI   64
#define TJ   64
#define NTILES 32

typedef unsigned long long u64;

// smem (floats): sQ 64x16f4, sK 64x16f4, sVd 64x32f4 (duplicated V),
// sR 128x16f4 (circular), sW 64x64 floats (XOR-swizzled)
#define SMEM_BYTES ((1024 + 1024 + 2048 + 2048) * 16 + 4096 * 4)

__device__ __forceinline__ u64 fma2(u64 a, u64 b, u64 c) {
    u64 d; asm("fma.rn.f32x2 %0, %1, %2, %3;" : "=l"(d) : "l"(a), "l"(b), "l"(c)); return d;
}
__device__ __forceinline__ u64 add2(u64 a, u64 b) {
    u64 d; asm("add.rn.f32x2 %0, %1, %2;" : "=l"(d) : "l"(a), "l"(b)); return d;
}
__device__ __forceinline__ float2 unpack2(u64 x) {
    float lo, hi; asm("mov.b64 {%0, %1}, %2;" : "=f"(lo), "=f"(hi) : "l"(x));
    return make_float2(lo, hi);
}

// XOR swizzle, float4 index for [row][c], c in 0..15.
__device__ __forceinline__ int sw(int row, int c) { return row * 16 + (c ^ (row & 15)); }

__global__ __launch_bounds__(256)
void fastmax_kernel(const float* __restrict__ q,
                    const float* __restrict__ k,
                    const float* __restrict__ v,
                    const float* __restrict__ rpe,
                    float* __restrict__ out)
{
    extern __shared__ float smem[];
    float4* sQ  = reinterpret_cast<float4*>(smem);     // 1024 f4, swizzled
    float4* sK  = sQ + 1024;                           // 1024 f4, swizzled
    float4* sVd = sK + 1024;                           // 2048 f4, duplicated pairs
    float4* sR  = sVd + 2048;                          // 2048 f4, swizzled, circular
    float*  sW  = reinterpret_cast<float*>(sR + 2048); // 64*64, XOR-by-j swizzle

    const int h    = blockIdx.y;
    const int tid  = threadIdx.x;
    const int wid  = tid >> 5;
    const int lane = tid & 31;
    // 8 x 4 warp footprint: ti has 8 distinct values per warp, tj has 4.
    const int ti = ((wid & 1) << 3) | (lane >> 2);   // 0..15
    const int tj = ((wid >> 1) << 2) | (lane & 3);   // 0..15

    const float4* gq = reinterpret_cast<const float4*>(q + (size_t)h * NSEQ * DIM);
    const float4* gk = reinterpret_cast<const float4*>(k + (size_t)h * NSEQ * DIM);
    const float4* gv = reinterpret_cast<const float4*>(v + (size_t)h * NSEQ * DIM);
    const float4* gr = reinterpret_cast<const float4*>(rpe);
    float4* gout     = reinterpret_cast<float4*>(out + (size_t)h * NSEQ * DIM);

    for (int half = 0; half < 2; half++) {
        const int itile = (half == 0) ? (int)blockIdx.x : (NTILES - 1 - (int)blockIdx.x);
        const int i0 = itile * TI;

        __syncthreads();   // previous half's phase B fully done before sQ overwrite
        // ---- load Q tile (swizzled) ----
        #pragma unroll
        for (int it = 0; it < 4; it++) {
            int idx = tid + it * 256;
            int row = idx >> 4, c = idx & 15;
            sQ[sw(row, c)] = gq[(i0 + row) * 16 + c];
        }

        // phase-B accumulators: o[rp][c] packs rows (4ti+2rp, 4ti+2rp+1), col 4tj+c
        u64 o00 = 0, o01 = 0, o02 = 0, o03 = 0;
        u64 o10 = 0, o11 = 0, o12 = 0, o13 = 0;
        u64 dac0 = 0, dac1 = 0;

        int roff = 0;   // circular offset of the RPE band buffer (0 or 64)

        const int njt = itile + 1;
        for (int jt = 0; jt < njt; jt++) {
            const int j0 = jt * TJ;

            __syncthreads();   // previous phase B / A reads done; Q fill visible

            // ---- fill K (swizzled) and duplicated V ----
            #pragma unroll
            for (int it = 0; it < 4; it++) {
                int idx = tid + it * 256;
                int row = idx >> 4, c = idx & 15;
                float4 kv4 = gk[(j0 + row) * 16 + c];
                float4 vv4 = gv[(j0 + row) * 16 + c];
                sK[sw(row, c)] = kv4;
                sVd[row * 32 + 2 * c]     = make_float4(vv4.x, vv4.x, vv4.y, vv4.y);
                sVd[row * 32 + 2 * c + 1] = make_float4(vv4.z, vv4.z, vv4.w, vv4.w);
            }
            // ---- fill RPE band (circular): logical row li holds rel = rmin + li,
            //      physical row p = (li + roff) & 127 ----
            const int rmin = i0 - j0 + (NSEQ - TJ);
            if (jt == 0) {
                // full fill, roff = 0
                #pragma unroll
                for (int it = 0; it < 8; it++) {
                    int idx = tid + it * 256;
                    int row = idx >> 4, c = idx & 15;
                    int rr  = rmin + (row < 127 ? row : 126);   // row 127 is pad
                    sR[sw(row, c)] = gr[rr * 16 + c];
                }
            } else {
                // band shifted down by 64: only rows li = 0..63 are new
                roff ^= 64;
                #pragma unroll
                for (int it = 0; it < 4; it++) {
                    int idx = tid + it * 256;
                    int row = idx >> 4, c = idx & 15;        // li = row in 0..63
                    sR[sw(roff + row, c)] = gr[(rmin + row) * 16 + c];
                }
            }
            __syncthreads();

            // ---- phase A: packed f32x2 score accumulation ----
            u64 acc[4][4];
            #pragma unroll
            for (int a = 0; a < 4; a++)
                #pragma unroll
                for (int b = 0; b < 4; b++) acc[a][b] = 0ull;

            const int rbase = ti - tj + (TJ - 1);   // in [48, 78]
            #pragma unroll 2
            for (int dg = 0; dg < 16; dg++) {
                ulonglong2 qv[4], kv[4], rv[7];
                #pragma unroll
                for (int a = 0; a < 4; a++)
                    qv[a] = *reinterpret_cast<const ulonglong2*>(&sQ[sw(ti + 16 * a, dg)]);
                #pragma unroll
                for (int b = 0; b < 4; b++)
                    kv[b] = *reinterpret_cast<const ulonglong2*>(&sK[sw(tj + 16 * b, dg)]);
                #pragma unroll
                for (int t = 0; t < 7; t++) {
                    int p = (rbase + 16 * (t - 3) + roff) & 127;
                    rv[t] = *reinterpret_cast<const ulonglong2*>(&sR[sw(p, dg)]);
                }
                #pragma unroll
                for (int a = 0; a < 4; a++) {
                    #pragma unroll
                    for (int b = 0; b < 4; b++) {
                        const ulonglong2 rr = rv[a - b + 3];
                        u64 t0 = add2(kv[b].x, rr.x);
                        u64 t1 = add2(kv[b].y, rr.y);
                        acc[a][b] = fma2(qv[a].x, t0, acc[a][b]);
                        acc[a][b] = fma2(qv[a].y, t1, acc[a][b]);
                    }
                }
            }

            // ---- weight + causal mask, store to sW (XOR-by-j swizzle) ----
            {
                const int i4b = ti >> 2, ilo = ti & 3;
                #pragma unroll
                for (int a = 0; a < 4; a++) {
                    const int gi = i0 + ti + 16 * a;
                    const int i4 = i4b + 4 * a;
                    #pragma unroll
                    for (int b = 0; b < 4; b++) {
                        const int gj = j0 + tj + 16 * b;
                        float2 p = unpack2(acc[a][b]);
                        float s = p.x + p.y;
                        float w = fmaf(0.5f * s, s, 1.0f + s);
                        if (gj > gi) w = 0.0f;
                        sW[(tj + 16 * b) * 64 + (((i4 ^ tj) << 2) | ilo)] = w;
                    }
                }
            }
            __syncthreads();

            // ---- phase B: out += W * V (packed row-pairs x broadcast-V) ----
            const ulonglong2* vd = reinterpret_cast<const ulonglong2*>(sVd);
            #pragma unroll 8
            for (int j = 0; j < TJ; j++) {
                const ulonglong2 wv = *reinterpret_cast<const ulonglong2*>(
                    &sW[j * 64 + ((ti ^ (j & 15)) << 2)]);   // (w0,w1),(w2,w3)
                const ulonglong2 va = vd[j * 32 + 2 * tj];       // (v0,v0),(v1,v1)
                const ulonglong2 vb = vd[j * 32 + 2 * tj + 1];   // (v2,v2),(v3,v3)
                o00 = fma2(wv.x, va.x, o00);
                o01 = fma2(wv.x, va.y, o01);
                o02 = fma2(wv.x, vb.x, o02);
                o03 = fma2(wv.x, vb.y, o03);
                o10 = fma2(wv.y, va.x, o10);
                o11 = fma2(wv.y, va.y, o11);
                o12 = fma2(wv.y, vb.x, o12);
                o13 = fma2(wv.y, vb.y, o13);
                dac0 = add2(dac0, wv.x);
                dac1 = add2(dac1, wv.y);
            }
        }

        // ---- epilogue: normalize + write rows i0 + 4*ti + r, f4 col tj ----
        {
            float2 dlo = unpack2(dac0), dhi = unpack2(dac1);
            float2 c0l = unpack2(o00), c1l = unpack2(o01), c2l = unpack2(o02), c3l = unpack2(o03);
            float2 c0h = unpack2(o10), c1h = unpack2(o11), c2h = unpack2(o12), c3h = unpack2(o13);
            float inv; float4 r;

            inv = 1.0f / dlo.x;
            r = make_float4(c0l.x * inv, c1l.x * inv, c2l.x * inv, c3l.x * inv);
            gout[(i0 + 4 * ti + 0) * 16 + tj] = r;
            inv = 1.0f / dlo.y;
            r = make_float4(c0l.y * inv, c1l.y * inv, c2l.y * inv, c3l.y * inv);
            gout[(i0 + 4 * ti + 1) * 16 + tj] = r;
            inv = 1.0f / dhi.x;
            r = make_float4(c0h.x * inv, c1h.x * inv, c2h.x * inv, c3h.x * inv);
            gout[(i0 + 4 * ti + 2) * 16 + tj] = r;
            inv = 1.0f / dhi.y;
            r = make_float4(c0h.y * inv, c1h.y * inv, c2h.y * inv, c3h.y * inv);
            gout[(i0 + 4 * ti + 3) * 16 + tj] = r;
        }
    }
}

extern "C" void kernel_launch(void* const* d_in, const int* in_sizes, int n_in,
                              void* d_out, int out_size)
{
    (void)in_sizes; (void)n_in; (void)out_size;
    const float* q   = (const float*)d_in[0];
    const float* k   = (const float*)d_in[1];
    const float* v   = (const float*)d_in[2];
    const float* rpe = (const float*)d_in[3];
    float* out = (float*)d_out;

    cudaFuncSetAttribute(fastmax_kernel,
                         cudaFuncAttributeMaxDynamicSharedMemorySize, SMEM_BYTES);
    fastmax_kernel<<<dim3(16, 8), 256, SMEM_BYTES>>>(q, k, v, rpe, out);
}

// round 9
// speedup vs baseline: 1.7898x; 1.1566x over previous
#include <cuda_runtime.h>
#include <cuda_bf16.h>

// fastmax attention, B=1, H=8, N=2048, D=64, causal, with RPE.
// s[i,j] = q_i . (k_j + rpe[i-j+N-1]);  w = 1 + s + s^2/2 (j<=i else 0)
// out[i] = (sum_j w*v_j) / (sum_j w)
//
// Decomposition: block = (head, i-tile t, chunk of <=8 consecutive j-tiles).
// 80 blocks/head * 8 heads = 640 blocks; 96KB smem + 128 regs -> 2 CTAs/SM.
// Blocks write unnormalized partial (num, den) into fixed slots; a reduce
// kernel sums <=4 slots per i-tile and normalizes. Packed f32x2 math.

#define NSEQ 2048
#define DIM  64
#define TI   64
#define TJ   64
#define NTILES 32
#define CHUNK 8
#define MAXSLOT 4

typedef unsigned long long u64;

// smem (float4 units): sQ 1024, sK 1024, sV 1024, sR 2048 (circular) + sW 4096 floats
#define SMEM_BYTES ((1024 + 1024 + 1024 + 2048) * 16 + 4096 * 4)

// partial scratch: [head][itile][slot] -> 64x64 num (f4) + 64 den.
// Zero-initialized at module load; unused slots are never written, used slots
// are fully overwritten every launch (deterministic across graph replays).
__device__ float4 g_pnum[8 * 32 * MAXSLOT * 1024] = {};   // 16 MB
__device__ float  g_pden[8 * 32 * MAXSLOT * 64]   = {};

__device__ __forceinline__ u64 fma2(u64 a, u64 b, u64 c) {
    u64 d; asm("fma.rn.f32x2 %0, %1, %2, %3;" : "=l"(d) : "l"(a), "l"(b), "l"(c)); return d;
}
__device__ __forceinline__ u64 add2(u64 a, u64 b) {
    u64 d; asm("add.rn.f32x2 %0, %1, %2;" : "=l"(d) : "l"(a), "l"(b)); return d;
}
__device__ __forceinline__ float2 unpack2(u64 x) {
    float lo, hi; asm("mov.b64 {%0, %1}, %2;" : "=f"(lo), "=f"(hi) : "l"(x));
    return make_float2(lo, hi);
}
__device__ __forceinline__ u64 pack2(float lo, float hi) {
    u64 d; asm("mov.b64 %0, {%1, %2};" : "=l"(d) : "f"(lo), "f"(hi)); return d;
}

// XOR swizzle, float4 index for [row][c], c in 0..15.
__device__ __forceinline__ int sw(int row, int c) { return row * 16 + (c ^ (row & 15)); }

__global__ __launch_bounds__(256, 2)
void fastmax_partial(const float* __restrict__ q,
                     const float* __restrict__ k,
                     const float* __restrict__ v,
                     const float* __restrict__ rpe)
{
    extern __shared__ float smem[];
    float4* sQ = reinterpret_cast<float4*>(smem);     // 1024 f4, swizzled
    float4* sK = sQ + 1024;                           // 1024 f4, swizzled
    float4* sV = sK + 1024;                           // 1024 f4, plain
    float4* sR = sV + 1024;                           // 2048 f4, swizzled circular
    float*  sW = reinterpret_cast<float*>(sR + 2048); // 64*64, XOR-by-j swizzle

    const int h    = blockIdx.y;
    const int tid  = threadIdx.x;
    const int wid  = tid >> 5;
    const int lane = tid & 31;
    // 8 x 4 warp footprint: 8 distinct ti, 4 distinct tj per warp.
    const int ti = ((wid & 1) << 3) | (lane >> 2);   // 0..15
    const int tj = ((wid >> 1) << 2) | (lane & 3);   // 0..15

    // decode blockIdx.x (0..79) -> (itile t, chunk slot)
    int rem = blockIdx.x;
    int t = 0;
    for (;;) {
        int nb = (t + CHUNK) / CHUNK;   // ceil((t+1)/CHUNK)
        if (rem < nb) break;
        rem -= nb;
        t++;
    }
    const int slot = rem;
    const int jt0  = slot * CHUNK;
    const int jt1  = min(jt0 + CHUNK, t + 1);
    const int i0   = t * TI;

    const float4* gq = reinterpret_cast<const float4*>(q + (size_t)h * NSEQ * DIM);
    const float4* gk = reinterpret_cast<const float4*>(k + (size_t)h * NSEQ * DIM);
    const float4* gv = reinterpret_cast<const float4*>(v + (size_t)h * NSEQ * DIM);
    const float4* gr = reinterpret_cast<const float4*>(rpe);

    // ---- load Q tile (swizzled) ----
    #pragma unroll
    for (int it = 0; it < 4; it++) {
        int idx = tid + it * 256;
        int row = idx >> 4, c = idx & 15;
        sQ[sw(row, c)] = gq[(i0 + row) * 16 + c];
    }

    // phase-B accumulators: o[r][cp] packs cols (4tj+2cp, 4tj+2cp+1) of row 4ti+r
    u64 o00 = 0, o01 = 0, o10 = 0, o11 = 0;
    u64 o20 = 0, o21 = 0, o30 = 0, o31 = 0;
    float d0 = 0.f, d1 = 0.f, d2 = 0.f, d3 = 0.f;

    int roff = 0;
    bool first = true;

    for (int jt = jt0; jt < jt1; jt++) {
        const int j0 = jt * TJ;

        __syncthreads();   // prior phase A/B reads done; Q fill visible

        // ---- fill K (swizzled), V (plain) ----
        #pragma unroll
        for (int it = 0; it < 4; it++) {
            int idx = tid + it * 256;
            int row = idx >> 4, c = idx & 15;
            sK[sw(row, c)]   = gk[(j0 + row) * 16 + c];
            sV[row * 16 + c] = gv[(j0 + row) * 16 + c];
        }
        // ---- fill RPE band (circular): logical li holds rel = rmin + li ----
        const int rmin = i0 - j0 + (NSEQ - TJ);
        if (first) {
            first = false;
            #pragma unroll
            for (int it = 0; it < 8; it++) {
                int idx = tid + it * 256;
                int row = idx >> 4, c = idx & 15;
                int rr  = rmin + (row < 127 ? row : 126);   // row 127 is pad
                sR[sw(row, c)] = gr[rr * 16 + c];
            }
        } else {
            roff ^= 64;   // band shifted down by 64: rows li = 0..63 are new
            #pragma unroll
            for (int it = 0; it < 4; it++) {
                int idx = tid + it * 256;
                int row = idx >> 4, c = idx & 15;
                sR[sw(roff + row, c)] = gr[(rmin + row) * 16 + c];
            }
        }
        __syncthreads();

        // ---- phase A: packed f32x2 score accumulation ----
        u64 acc[4][4];
        #pragma unroll
        for (int a = 0; a < 4; a++)
            #pragma unroll
            for (int b = 0; b < 4; b++) acc[a][b] = 0ull;

        const int rbase = ti - tj + (TJ - 1);   // in [48, 78]
        #pragma unroll 2
        for (int dg = 0; dg < 16; dg++) {
            ulonglong2 qv[4], kv[4], rv[7];
            #pragma unroll
            for (int a = 0; a < 4; a++)
                qv[a] = *reinterpret_cast<const ulonglong2*>(&sQ[sw(ti + 16 * a, dg)]);
            #pragma unroll
            for (int b = 0; b < 4; b++)
                kv[b] = *reinterpret_cast<const ulonglong2*>(&sK[sw(tj + 16 * b, dg)]);
            #pragma unroll
            for (int tt = 0; tt < 7; tt++) {
                int p = (rbase + 16 * (tt - 3) + roff) & 127;
                rv[tt] = *reinterpret_cast<const ulonglong2*>(&sR[sw(p, dg)]);
            }
            #pragma unroll
            for (int a = 0; a < 4; a++) {
                #pragma unroll
                for (int b = 0; b < 4; b++) {
                    const ulonglong2 rr = rv[a - b + 3];
                    u64 t0 = add2(kv[b].x, rr.x);
                    u64 t1 = add2(kv[b].y, rr.y);
                    acc[a][b] = fma2(qv[a].x, t0, acc[a][b]);
                    acc[a][b] = fma2(qv[a].y, t1, acc[a][b]);
                }
            }
        }

        // ---- weight + causal mask, store to sW (XOR-by-j swizzle) ----
        {
            const int i4b = ti >> 2, ilo = ti & 3;
            #pragma unroll
            for (int a = 0; a < 4; a++) {
                const int gi = i0 + ti + 16 * a;
                const int i4 = i4b + 4 * a;
                #pragma unroll
                for (int b = 0; b < 4; b++) {
                    const int gj = j0 + tj + 16 * b;
                    float2 p = unpack2(acc[a][b]);
                    float s = p.x + p.y;
                    float w = fmaf(0.5f * s, s, 1.0f + s);
                    if (gj > gi) w = 0.0f;
                    sW[(tj + 16 * b) * 64 + (((i4 ^ tj) << 2) | ilo)] = w;
                }
            }
        }
        __syncthreads();

        // ---- phase B: out += W * V (row-broadcast w x natural V col-pairs) ----
        #pragma unroll 8
        for (int j = 0; j < TJ; j++) {
            const float4 wq = *reinterpret_cast<const float4*>(
                &sW[j * 64 + ((ti ^ (j & 15)) << 2)]);       // w for rows 4ti..4ti+3
            const ulonglong2 vp = *reinterpret_cast<const ulonglong2*>(
                &sV[j * 16 + tj]);                           // (v0,v1),(v2,v3)
            u64 w0 = pack2(wq.x, wq.x);
            u64 w1 = pack2(wq.y, wq.y);
            u64 w2 = pack2(wq.z, wq.z);
            u64 w3 = pack2(wq.w, wq.w);
            o00 = fma2(w0, vp.x, o00); o01 = fma2(w0, vp.y, o01);
            o10 = fma2(w1, vp.x, o10); o11 = fma2(w1, vp.y, o11);
            o20 = fma2(w2, vp.x, o20); o21 = fma2(w2, vp.y, o21);
            o30 = fma2(w3, vp.x, o30); o31 = fma2(w3, vp.y, o31);
            d0 += wq.x; d1 += wq.y; d2 += wq.z; d3 += wq.w;
        }
    }

    // ---- write unnormalized partials ----
    {
        const int sb = ((h * NTILES + t) * MAXSLOT + slot);
        float4* pn = &g_pnum[(size_t)sb * 1024];
        float2 a0 = unpack2(o00), b0 = unpack2(o01);
        float2 a1 = unpack2(o10), b1 = unpack2(o11);
        float2 a2 = unpack2(o20), b2 = unpack2(o21);
        float2 a3 = unpack2(o30), b3 = unpack2(o31);
        pn[(4 * ti + 0) * 16 + tj] = make_float4(a0.x, a0.y, b0.x, b0.y);
        pn[(4 * ti + 1) * 16 + tj] = make_float4(a1.x, a1.y, b1.x, b1.y);
        pn[(4 * ti + 2) * 16 + tj] = make_float4(a2.x, a2.y, b2.x, b2.y);
        pn[(4 * ti + 3) * 16 + tj] = make_float4(a3.x, a3.y, b3.x, b3.y);
        if (tj == 0) {
            float* pd = &g_pden[(size_t)sb * 64];
            pd[4 * ti + 0] = d0;
            pd[4 * ti + 1] = d1;
            pd[4 * ti + 2] = d2;
            pd[4 * ti + 3] = d3;
        }
    }
}

__global__ __launch_bounds__(256)
void fastmax_reduce(float* __restrict__ out)
{
    const int gi = blockIdx.x * 256 + threadIdx.x;  // 0..262143 (f4 elements)
    const int rg = gi >> 4;                         // global row: h*2048 + i
    const int c4 = gi & 15;
    const int hh = rg >> 11;
    const int i  = rg & 2047;
    const int t  = i >> 6;
    const int r  = i & 63;

    const size_t nb = ((size_t)(hh * NTILES + t) * MAXSLOT) * 1024 + r * 16 + c4;
    const size_t db = ((size_t)(hh * NTILES + t) * MAXSLOT) * 64 + r;

    float4 a = make_float4(0.f, 0.f, 0.f, 0.f);
    float den = 0.f;
    #pragma unroll
    for (int s = 0; s < MAXSLOT; s++) {
        float4 p = g_pnum[nb + (size_t)s * 1024];
        a.x += p.x; a.y += p.y; a.z += p.z; a.w += p.w;
        den += g_pden[db + (size_t)s * 64];
    }
    const float inv = 1.0f / den;
    reinterpret_cast<float4*>(out)[rg * 16 + c4] =
        make_float4(a.x * inv, a.y * inv, a.z * inv, a.w * inv);
}

extern "C" void kernel_launch(void* const* d_in, const int* in_sizes, int n_in,
                              void* d_out, int out_size)
{
    (void)in_sizes; (void)n_in; (void)out_size;
    const float* q   = (const float*)d_in[0];
    const float* k   = (const float*)d_in[1];
    const float* v   = (const float*)d_in[2];
    const float* rpe = (const float*)d_in[3];
    float* out = (float*)d_out;

    cudaFuncSetAttribute(fastmax_partial,
                         cudaFuncAttributeMaxDynamicSharedMemorySize, SMEM_BYTES);
    fastmax_partial<<<dim3(80, 8), 256, SMEM_BYTES>>>(q, k, v, rpe);
    fastmax_reduce<<<1024, 256>>>(out);
}

// round 10
// speedup vs baseline: 1.8198x; 1.0168x over previous
#include <cuda_runtime.h>
#include <cuda_bf16.h>
#include <cstdint>

// fastmax attention, B=1, H=8, N=2048, D=64, causal, with RPE.
// s[i,j] = q_i . (k_j + rpe[i-j+N-1]);  w = 1 + s + s^2/2 (j<=i else 0)
// out[i] = (sum_j w*v_j) / (sum_j w)
//
// Decomposition: block = (head, i-tile t, chunk of <=8 consecutive j-tiles).
// LPT order: largest chunks get the smallest blockIdx.x so they launch first.
// 80 blocks/head * 8 heads = 640 blocks; 96KB smem + 128 regs -> 2 CTAs/SM.
// Fills use cp.async (LDGSTS). Partials into fixed slots; reduce normalizes.

#define NSEQ 2048
#define DIM  64
#define TI   64
#define TJ   64
#define NTILES 32
#define CHUNK 8
#define MAXSLOT 4

typedef unsigned long long u64;

// smem (float4 units): sQ 1024, sK 1024, sV 1024, sR 2048 (circular) + sW 4096 floats
#define SMEM_BYTES ((1024 + 1024 + 1024 + 2048) * 16 + 4096 * 4)

// partial scratch: [head][itile][slot] -> 64x64 num (f4) + 64 den.
// Used slots fully overwritten each launch; unused slots never read.
__device__ float4 g_pnum[8 * 32 * MAXSLOT * 1024] = {};   // 16 MB
__device__ float  g_pden[8 * 32 * MAXSLOT * 64]   = {};

__device__ __forceinline__ u64 fma2(u64 a, u64 b, u64 c) {
    u64 d; asm("fma.rn.f32x2 %0, %1, %2, %3;" : "=l"(d) : "l"(a), "l"(b), "l"(c)); return d;
}
__device__ __forceinline__ u64 add2(u64 a, u64 b) {
    u64 d; asm("add.rn.f32x2 %0, %1, %2;" : "=l"(d) : "l"(a), "l"(b)); return d;
}
__device__ __forceinline__ float2 unpack2(u64 x) {
    float lo, hi; asm("mov.b64 {%0, %1}, %2;" : "=f"(lo), "=f"(hi) : "l"(x));
    return make_float2(lo, hi);
}
__device__ __forceinline__ u64 pack2(float lo, float hi) {
    u64 d; asm("mov.b64 %0, {%1, %2};" : "=l"(d) : "f"(lo), "f"(hi)); return d;
}
__device__ __forceinline__ uint32_t smem_u32(const void* p) {
    return (uint32_t)__cvta_generic_to_shared(p);
}
// 16B async copy global -> shared
__device__ __forceinline__ void cp16(uint32_t dst, const void* src) {
    asm volatile("cp.async.cg.shared.global [%0], [%1], 16;" :: "r"(dst), "l"(src));
}
__device__ __forceinline__ void cp_commit_wait() {
    asm volatile("cp.async.commit_group;");
    asm volatile("cp.async.wait_group 0;");
}

// XOR swizzle, float4 index for [row][c], c in 0..15.
__device__ __forceinline__ int sw(int row, int c) { return row * 16 + (c ^ (row & 15)); }

__global__ __launch_bounds__(256, 2)
void fastmax_partial(const float* __restrict__ q,
                     const float* __restrict__ k,
                     const float* __restrict__ v,
                     const float* __restrict__ rpe)
{
    extern __shared__ float smem[];
    float4* sQ = reinterpret_cast<float4*>(smem);     // 1024 f4, swizzled
    float4* sK = sQ + 1024;                           // 1024 f4, swizzled
    float4* sV = sK + 1024;                           // 1024 f4, plain
    float4* sR = sV + 1024;                           // 2048 f4, swizzled circular
    float*  sW = reinterpret_cast<float*>(sR + 2048); // 64*64, XOR-by-j swizzle

    const uint32_t sKu = smem_u32(sK);
    const uint32_t sVu = smem_u32(sV);
    const uint32_t sRu = smem_u32(sR);

    const int h    = blockIdx.y;
    const int tid  = threadIdx.x;
    const int wid  = tid >> 5;
    const int lane = tid & 31;
    // 8 x 4 warp footprint: 8 distinct ti, 4 distinct tj per warp.
    const int ti = ((wid & 1) << 3) | (lane >> 2);   // 0..15
    const int tj = ((wid >> 1) << 2) | (lane & 3);   // 0..15

    // decode blockIdx.x (0..79) -> (itile t, chunk slot), LPT: t DESCENDING
    // so 8-unit chunks (large t) occupy the smallest bids and launch first.
    int rem = blockIdx.x;
    int t = NTILES - 1;
    for (;;) {
        int nb = (t + CHUNK) >> 3;   // ceil((t+1)/CHUNK)
        if (rem < nb) break;
        rem -= nb;
        t--;
    }
    const int slot = rem;
    const int jt0  = slot * CHUNK;
    const int jt1  = min(jt0 + CHUNK, t + 1);
    const int i0   = t * TI;

    const float4* gq = reinterpret_cast<const float4*>(q + (size_t)h * NSEQ * DIM);
    const float4* gk = reinterpret_cast<const float4*>(k + (size_t)h * NSEQ * DIM);
    const float4* gv = reinterpret_cast<const float4*>(v + (size_t)h * NSEQ * DIM);
    const float4* gr = reinterpret_cast<const float4*>(rpe);

    // ---- load Q tile (swizzled) ----
    #pragma unroll
    for (int it = 0; it < 4; it++) {
        int idx = tid + it * 256;
        int row = idx >> 4, c = idx & 15;
        sQ[sw(row, c)] = gq[(i0 + row) * 16 + c];
    }

    // phase-B accumulators: o[r][cp] packs cols (4tj+2cp, 4tj+2cp+1) of row 4ti+r
    u64 o00 = 0, o01 = 0, o10 = 0, o11 = 0;
    u64 o20 = 0, o21 = 0, o30 = 0, o31 = 0;
    float d0 = 0.f, d1 = 0.f, d2 = 0.f, d3 = 0.f;

    int roff = 0;
    bool first = true;

    for (int jt = jt0; jt < jt1; jt++) {
        const int j0 = jt * TJ;

        __syncthreads();   // prior phase A/B reads done; Q fill visible

        // ---- fill K (swizzled), V (plain) via cp.async ----
        #pragma unroll
        for (int it = 0; it < 4; it++) {
            int idx = tid + it * 256;
            int row = idx >> 4, c = idx & 15;
            cp16(sKu + sw(row, c) * 16,   &gk[(j0 + row) * 16 + c]);
            cp16(sVu + (row * 16 + c) * 16, &gv[(j0 + row) * 16 + c]);
        }
        // ---- fill RPE band (circular): logical li holds rel = rmin + li ----
        const int rmin = i0 - j0 + (NSEQ - TJ);
        if (first) {
            first = false;
            #pragma unroll
            for (int it = 0; it < 8; it++) {
                int idx = tid + it * 256;
                int row = idx >> 4, c = idx & 15;
                int rr  = rmin + (row < 127 ? row : 126);   // row 127 is pad
                cp16(sRu + sw(row, c) * 16, &gr[rr * 16 + c]);
            }
        } else {
            roff ^= 64;   // band shifted down by 64: rows li = 0..63 are new
            #pragma unroll
            for (int it = 0; it < 4; it++) {
                int idx = tid + it * 256;
                int row = idx >> 4, c = idx & 15;
                cp16(sRu + sw(roff + row, c) * 16, &gr[(rmin + row) * 16 + c]);
            }
        }
        cp_commit_wait();
        __syncthreads();

        // ---- phase A: packed f32x2 score accumulation ----
        u64 acc[4][4];
        #pragma unroll
        for (int a = 0; a < 4; a++)
            #pragma unroll
            for (int b = 0; b < 4; b++) acc[a][b] = 0ull;

        const int rbase = ti - tj + (TJ - 1);   // in [48, 78]
        #pragma unroll 2
        for (int dg = 0; dg < 16; dg++) {
            ulonglong2 qv[4], kv[4], rv[7];
            #pragma unroll
            for (int a = 0; a < 4; a++)
                qv[a] = *reinterpret_cast<const ulonglong2*>(&sQ[sw(ti + 16 * a, dg)]);
            #pragma unroll
            for (int b = 0; b < 4; b++)
                kv[b] = *reinterpret_cast<const ulonglong2*>(&sK[sw(tj + 16 * b, dg)]);
            #pragma unroll
            for (int tt = 0; tt < 7; tt++) {
                int p = (rbase + 16 * (tt - 3) + roff) & 127;
                rv[tt] = *reinterpret_cast<const ulonglong2*>(&sR[sw(p, dg)]);
            }
            #pragma unroll
            for (int a = 0; a < 4; a++) {
                #pragma unroll
                for (int b = 0; b < 4; b++) {
                    const ulonglong2 rr = rv[a - b + 3];
                    u64 t0 = add2(kv[b].x, rr.x);
                    u64 t1 = add2(kv[b].y, rr.y);
                    acc[a][b] = fma2(qv[a].x, t0, acc[a][b]);
                    acc[a][b] = fma2(qv[a].y, t1, acc[a][b]);
                }
            }
        }

        // ---- weight + causal mask, store to sW (XOR-by-j swizzle) ----
        {
            const int i4b = ti >> 2, ilo = ti & 3;
            #pragma unroll
            for (int a = 0; a < 4; a++) {
                const int gi = i0 + ti + 16 * a;
                const int i4 = i4b + 4 * a;
                #pragma unroll
                for (int b = 0; b < 4; b++) {
                    const int gj = j0 + tj + 16 * b;
                    float2 p = unpack2(acc[a][b]);
                    float s = p.x + p.y;
                    float w = fmaf(0.5f * s, s, 1.0f + s);
                    if (gj > gi) w = 0.0f;
                    sW[(tj + 16 * b) * 64 + (((i4 ^ tj) << 2) | ilo)] = w;
                }
            }
        }
        __syncthreads();

        // ---- phase B: out += W * V (row-broadcast w x natural V col-pairs) ----
        #pragma unroll 8
        for (int j = 0; j < TJ; j++) {
            const float4 wq = *reinterpret_cast<const float4*>(
                &sW[j * 64 + ((ti ^ (j & 15)) << 2)]);       // w for rows 4ti..4ti+3
            const ulonglong2 vp = *reinterpret_cast<const ulonglong2*>(
                &sV[j * 16 + tj]);                           // (v0,v1),(v2,v3)
            u64 w0 = pack2(wq.x, wq.x);
            u64 w1 = pack2(wq.y, wq.y);
            u64 w2 = pack2(wq.z, wq.z);
            u64 w3 = pack2(wq.w, wq.w);
            o00 = fma2(w0, vp.x, o00); o01 = fma2(w0, vp.y, o01);
            o10 = fma2(w1, vp.x, o10); o11 = fma2(w1, vp.y, o11);
            o20 = fma2(w2, vp.x, o20); o21 = fma2(w2, vp.y, o21);
            o30 = fma2(w3, vp.x, o30); o31 = fma2(w3, vp.y, o31);
            d0 += wq.x; d1 += wq.y; d2 += wq.z; d3 += wq.w;
        }
    }

    // ---- write unnormalized partials ----
    {
        const int sb = ((h * NTILES + t) * MAXSLOT + slot);
        float4* pn = &g_pnum[(size_t)sb * 1024];
        float2 a0 = unpack2(o00), b0 = unpack2(o01);
        float2 a1 = unpack2(o10), b1 = unpack2(o11);
        float2 a2 = unpack2(o20), b2 = unpack2(o21);
        float2 a3 = unpack2(o30), b3 = unpack2(o31);
        pn[(4 * ti + 0) * 16 + tj] = make_float4(a0.x, a0.y, b0.x, b0.y);
        pn[(4 * ti + 1) * 16 + tj] = make_float4(a1.x, a1.y, b1.x, b1.y);
        pn[(4 * ti + 2) * 16 + tj] = make_float4(a2.x, a2.y, b2.x, b2.y);
        pn[(4 * ti + 3) * 16 + tj] = make_float4(a3.x, a3.y, b3.x, b3.y);
        if (tj == 0) {
            float* pd = &g_pden[(size_t)sb * 64];
            pd[4 * ti + 0] = d0;
            pd[4 * ti + 1] = d1;
            pd[4 * ti + 2] = d2;
            pd[4 * ti + 3] = d3;
        }
    }
}

__global__ __launch_bounds__(256)
void fastmax_reduce(float* __restrict__ out)
{
    const int gi = blockIdx.x * 256 + threadIdx.x;  // 0..262143 (f4 elements)
    const int rg = gi >> 4;                         // global row: h*2048 + i
    const int c4 = gi & 15;
    const int hh = rg >> 11;
    const int i  = rg & 2047;
    const int t  = i >> 6;
    const int r  = i & 63;

    const int nslots = (t + CHUNK) >> 3;            // ceil((t+1)/CHUNK), 1..4

    const size_t nb = ((size_t)(hh * NTILES + t) * MAXSLOT) * 1024 + r * 16 + c4;
    const size_t db = ((size_t)(hh * NTILES + t) * MAXSLOT) * 64 + r;

    float4 a = make_float4(0.f, 0.f, 0.f, 0.f);
    float den = 0.f;
    for (int s = 0; s < nslots; s++) {
        float4 p = g_pnum[nb + (size_t)s * 1024];
        a.x += p.x; a.y += p.y; a.z += p.z; a.w += p.w;
        den += g_pden[db + (size_t)s * 64];
    }
    const float inv = 1.0f / den;
    reinterpret_cast<float4*>(out)[rg * 16 + c4] =
        make_float4(a.x * inv, a.y * inv, a.z * inv, a.w * inv);
}

extern "C" void kernel_launch(void* const* d_in, const int* in_sizes, int n_in,
                              void* d_out, int out_size)
{
    (void)in_sizes; (void)n_in; (void)out_size;
    const float* q   = (const float*)d_in[0];
    const float* k   = (const float*)d_in[1];
    const float* v   = (const float*)d_in[2];
    const float* rpe = (const float*)d_in[3];
    float* out = (float*)d_out;

    cudaFuncSetAttribute(fastmax_partial,
                         cudaFuncAttributeMaxDynamicSharedMemorySize, SMEM_BYTES);
    fastmax_partial<<<dim3(80, 8), 256, SMEM_BYTES>>>(q, k, v, rpe);
    fastmax_reduce<<<1024, 256>>>(out);
}

// round 11
// speedup vs baseline: 1.8218x; 1.0011x over previous
#include <cuda_runtime.h>
#include <cuda_bf16.h>
#include <cstdint>

// fastmax attention, B=1, H=8, N=2048, D=64, causal, with RPE.
// s[i,j] = q_i . (k_j + rpe[i-j+N-1]);  w = 1 + s + s^2/2 (j<=i else 0)
// out[i] = (sum_j w*v_j) / (sum_j w)
//
// Decomposition: block = (head, i-tile t, chunk of <=8 consecutive j-tiles).
// LPT order: largest chunks get the smallest blockIdx.x so they launch first.
// 80 blocks/head * 8 heads = 640 blocks; 96KB smem + 128 regs -> 2 CTAs/SM.
// Fills use cp.async (LDGSTS). Partials into fixed slots; reduce normalizes.

#define NSEQ 2048
#define DIM  64
#define TI   64
#define TJ   64
#define NTILES 32
#define CHUNK 8
#define MAXSLOT 4

typedef unsigned long long u64;

// smem (float4 units): sQ 1024, sK 1024, sV 1024, sR 2048 (circular) + sW 4096 floats
#define SMEM_BYTES ((1024 + 1024 + 1024 + 2048) * 16 + 4096 * 4)

// partial scratch: [head][itile][slot] -> 64x64 num (f4) + 64 den.
// Used slots fully overwritten each launch; unused slots never read.
__device__ float4 g_pnum[8 * 32 * MAXSLOT * 1024] = {};   // 16 MB
__device__ float  g_pden[8 * 32 * MAXSLOT * 64]   = {};

__device__ __forceinline__ u64 fma2(u64 a, u64 b, u64 c) {
    u64 d; asm("fma.rn.f32x2 %0, %1, %2, %3;" : "=l"(d) : "l"(a), "l"(b), "l"(c)); return d;
}
__device__ __forceinline__ u64 add2(u64 a, u64 b) {
    u64 d; asm("add.rn.f32x2 %0, %1, %2;" : "=l"(d) : "l"(a), "l"(b)); return d;
}
__device__ __forceinline__ float2 unpack2(u64 x) {
    float lo, hi; asm("mov.b64 {%0, %1}, %2;" : "=f"(lo), "=f"(hi) : "l"(x));
    return make_float2(lo, hi);
}
__device__ __forceinline__ u64 pack2(float lo, float hi) {
    u64 d; asm("mov.b64 %0, {%1, %2};" : "=l"(d) : "f"(lo), "f"(hi)); return d;
}
__device__ __forceinline__ uint32_t smem_u32(const void* p) {
    return (uint32_t)__cvta_generic_to_shared(p);
}
// 16B async copy global -> shared
__device__ __forceinline__ void cp16(uint32_t dst, const void* src) {
    asm volatile("cp.async.cg.shared.global [%0], [%1], 16;" :: "r"(dst), "l"(src));
}
__device__ __forceinline__ void cp_commit_wait() {
    asm volatile("cp.async.commit_group;");
    asm volatile("cp.async.wait_group 0;");
}

// XOR swizzle, float4 index for [row][c], c in 0..15.
__device__ __forceinline__ int sw(int row, int c) { return row * 16 + (c ^ (row & 15)); }

__global__ __launch_bounds__(256, 2)
void fastmax_partial(const float* __restrict__ q,
                     const float* __restrict__ k,
                     const float* __restrict__ v,
                     const float* __restrict__ rpe)
{
    extern __shared__ float smem[];
    float4* sQ = reinterpret_cast<float4*>(smem);     // 1024 f4, swizzled
    float4* sK = sQ + 1024;                           // 1024 f4, swizzled
    float4* sV = sK + 1024;                           // 1024 f4, plain
    float4* sR = sV + 1024;                           // 2048 f4, swizzled circular
    float*  sW = reinterpret_cast<float*>(sR + 2048); // 64*64, XOR-by-j swizzle

    const uint32_t sKu = smem_u32(sK);
    const uint32_t sVu = smem_u32(sV);
    const uint32_t sRu = smem_u32(sR);

    const int h    = blockIdx.y;
    const int tid  = threadIdx.x;
    const int wid  = tid >> 5;
    const int lane = tid & 31;
    // 8 x 4 warp footprint: 8 distinct ti, 4 distinct tj per warp.
    const int ti = ((wid & 1) << 3) | (lane >> 2);   // 0..15
    const int tj = ((wid >> 1) << 2) | (lane & 3);   // 0..15

    // decode blockIdx.x (0..79) -> (itile t, chunk slot), LPT: t DESCENDING
    // so 8-unit chunks (large t) occupy the smallest bids and launch first.
    int rem = blockIdx.x;
    int t = NTILES - 1;
    for (;;) {
        int nb = (t + CHUNK) >> 3;   // ceil((t+1)/CHUNK)
        if (rem < nb) break;
        rem -= nb;
        t--;
    }
    const int slot = rem;
    const int jt0  = slot * CHUNK;
    const int jt1  = min(jt0 + CHUNK, t + 1);
    const int i0   = t * TI;

    const float4* gq = reinterpret_cast<const float4*>(q + (size_t)h * NSEQ * DIM);
    const float4* gk = reinterpret_cast<const float4*>(k + (size_t)h * NSEQ * DIM);
    const float4* gv = reinterpret_cast<const float4*>(v + (size_t)h * NSEQ * DIM);
    const float4* gr = reinterpret_cast<const float4*>(rpe);

    // ---- load Q tile (swizzled) ----
    #pragma unroll
    for (int it = 0; it < 4; it++) {
        int idx = tid + it * 256;
        int row = idx >> 4, c = idx & 15;
        sQ[sw(row, c)] = gq[(i0 + row) * 16 + c];
    }

    // phase-B accumulators: o[r][cp] packs cols (4tj+2cp, 4tj+2cp+1) of row 4ti+r
    u64 o00 = 0, o01 = 0, o10 = 0, o11 = 0;
    u64 o20 = 0, o21 = 0, o30 = 0, o31 = 0;
    float d0 = 0.f, d1 = 0.f, d2 = 0.f, d3 = 0.f;

    int roff = 0;
    bool first = true;

    for (int jt = jt0; jt < jt1; jt++) {
        const int j0 = jt * TJ;

        __syncthreads();   // prior phase A/B reads done; Q fill visible

        // ---- fill K (swizzled), V (plain) via cp.async ----
        #pragma unroll
        for (int it = 0; it < 4; it++) {
            int idx = tid + it * 256;
            int row = idx >> 4, c = idx & 15;
            cp16(sKu + sw(row, c) * 16,   &gk[(j0 + row) * 16 + c]);
            cp16(sVu + (row * 16 + c) * 16, &gv[(j0 + row) * 16 + c]);
        }
        // ---- fill RPE band (circular): logical li holds rel = rmin + li ----
        const int rmin = i0 - j0 + (NSEQ - TJ);
        if (first) {
            first = false;
            #pragma unroll
            for (int it = 0; it < 8; it++) {
                int idx = tid + it * 256;
                int row = idx >> 4, c = idx & 15;
                int rr  = rmin + (row < 127 ? row : 126);   // row 127 is pad
                cp16(sRu + sw(row, c) * 16, &gr[rr * 16 + c]);
            }
        } else {
            roff ^= 64;   // band shifted down by 64: rows li = 0..63 are new
            #pragma unroll
            for (int it = 0; it < 4; it++) {
                int idx = tid + it * 256;
                int row = idx >> 4, c = idx & 15;
                cp16(sRu + sw(roff + row, c) * 16, &gr[(rmin + row) * 16 + c]);
            }
        }
        cp_commit_wait();
        __syncthreads();

        // ---- phase A: packed f32x2 score accumulation ----
        u64 acc[4][4];
        #pragma unroll
        for (int a = 0; a < 4; a++)
            #pragma unroll
            for (int b = 0; b < 4; b++) acc[a][b] = 0ull;

        const int rbase = ti - tj + (TJ - 1);   // in [48, 78]
        #pragma unroll 2
        for (int dg = 0; dg < 16; dg++) {
            ulonglong2 qv[4], kv[4], rv[7];
            #pragma unroll
            for (int a = 0; a < 4; a++)
                qv[a] = *reinterpret_cast<const ulonglong2*>(&sQ[sw(ti + 16 * a, dg)]);
            #pragma unroll
            for (int b = 0; b < 4; b++)
                kv[b] = *reinterpret_cast<const ulonglong2*>(&sK[sw(tj + 16 * b, dg)]);
            #pragma unroll
            for (int tt = 0; tt < 7; tt++) {
                int p = (rbase + 16 * (tt - 3) + roff) & 127;
                rv[tt] = *reinterpret_cast<const ulonglong2*>(&sR[sw(p, dg)]);
            }
            #pragma unroll
            for (int a = 0; a < 4; a++) {
                #pragma unroll
                for (int b = 0; b < 4; b++) {
                    const ulonglong2 rr = rv[a - b + 3];
                    u64 t0 = add2(kv[b].x, rr.x);
                    u64 t1 = add2(kv[b].y, rr.y);
                    acc[a][b] = fma2(qv[a].x, t0, acc[a][b]);
                    acc[a][b] = fma2(qv[a].y, t1, acc[a][b]);
                }
            }
        }

        // ---- weight + causal mask, store to sW (XOR-by-j swizzle) ----
        {
            const int i4b = ti >> 2, ilo = ti & 3;
            #pragma unroll
            for (int a = 0; a < 4; a++) {
                const int gi = i0 + ti + 16 * a;
                const int i4 = i4b + 4 * a;
                #pragma unroll
                for (int b = 0; b < 4; b++) {
                    const int gj = j0 + tj + 16 * b;
                    float2 p = unpack2(acc[a][b]);
                    float s = p.x + p.y;
                    float w = fmaf(0.5f * s, s, 1.0f + s);
                    if (gj > gi) w = 0.0f;
                    sW[(tj + 16 * b) * 64 + (((i4 ^ tj) << 2) | ilo)] = w;
                }
            }
        }
        __syncthreads();

        // ---- phase B: out += W * V (row-broadcast w x natural V col-pairs) ----
        #pragma unroll 8
        for (int j = 0; j < TJ; j++) {
            const float4 wq = *reinterpret_cast<const float4*>(
                &sW[j * 64 + ((ti ^ (j & 15)) << 2)]);       // w for rows 4ti..4ti+3
            const ulonglong2 vp = *reinterpret_cast<const ulonglong2*>(
                &sV[j * 16 + tj]);                           // (v0,v1),(v2,v3)
            u64 w0 = pack2(wq.x, wq.x);
            u64 w1 = pack2(wq.y, wq.y);
            u64 w2 = pack2(wq.z, wq.z);
            u64 w3 = pack2(wq.w, wq.w);
            o00 = fma2(w0, vp.x, o00); o01 = fma2(w0, vp.y, o01);
            o10 = fma2(w1, vp.x, o10); o11 = fma2(w1, vp.y, o11);
            o20 = fma2(w2, vp.x, o20); o21 = fma2(w2, vp.y, o21);
            o30 = fma2(w3, vp.x, o30); o31 = fma2(w3, vp.y, o31);
            d0 += wq.x; d1 += wq.y; d2 += wq.z; d3 += wq.w;
        }
    }

    // ---- write unnormalized partials ----
    {
        const int sb = ((h * NTILES + t) * MAXSLOT + slot);
        float4* pn = &g_pnum[(size_t)sb * 1024];
        float2 a0 = unpack2(o00), b0 = unpack2(o01);
        float2 a1 = unpack2(o10), b1 = unpack2(o11);
        float2 a2 = unpack2(o20), b2 = unpack2(o21);
        float2 a3 = unpack2(o30), b3 = unpack2(o31);
        pn[(4 * ti + 0) * 16 + tj] = make_float4(a0.x, a0.y, b0.x, b0.y);
        pn[(4 * ti + 1) * 16 + tj] = make_float4(a1.x, a1.y, b1.x, b1.y);
        pn[(4 * ti + 2) * 16 + tj] = make_float4(a2.x, a2.y, b2.x, b2.y);
        pn[(4 * ti + 3) * 16 + tj] = make_float4(a3.x, a3.y, b3.x, b3.y);
        if (tj == 0) {
            float* pd = &g_pden[(size_t)sb * 64];
            pd[4 * ti + 0] = d0;
            pd[4 * ti + 1] = d1;
            pd[4 * ti + 2] = d2;
            pd[4 * ti + 3] = d3;
        }
    }
}

__global__ __launch_bounds__(256)
void fastmax_reduce(float* __restrict__ out)
{
    const int gi = blockIdx.x * 256 + threadIdx.x;  // 0..262143 (f4 elements)
    const int rg = gi >> 4;                         // global row: h*2048 + i
    const int c4 = gi & 15;
    const int hh = rg >> 11;
    const int i  = rg & 2047;
    const int t  = i >> 6;
    const int r  = i & 63;

    const int nslots = (t + CHUNK) >> 3;            // ceil((t+1)/CHUNK), 1..4

    const size_t nb = ((size_t)(hh * NTILES + t) * MAXSLOT) * 1024 + r * 16 + c4;
    const size_t db = ((size_t)(hh * NTILES + t) * MAXSLOT) * 64 + r;

    float4 a = make_float4(0.f, 0.f, 0.f, 0.f);
    float den = 0.f;
    for (int s = 0; s < nslots; s++) {
        float4 p = g_pnum[nb + (size_t)s * 1024];
        a.x += p.x; a.y += p.y; a.z += p.z; a.w += p.w;
        den += g_pden[db + (size_t)s * 64];
    }
    const float inv = 1.0f / den;
    reinterpret_cast<float4*>(out)[rg * 16 + c4] =
        make_float4(a.x * inv, a.y * inv, a.z * inv, a.w * inv);
}

extern "C" void kernel_launch(void* const* d_in, const int* in_sizes, int n_in,
                              void* d_out, int out_size)
{
    (void)in_sizes; (void)n_in; (void)out_size;
    const float* q   = (const float*)d_in[0];
    const float* k   = (const float*)d_in[1];
    const float* v   = (const float*)d_in[2];
    const float* rpe = (const float*)d_in[3];
    float* out = (float*)d_out;

    cudaFuncSetAttribute(fastmax_partial,
                         cudaFuncAttributeMaxDynamicSharedMemorySize, SMEM_BYTES);
    fastmax_partial<<<dim3(80, 8), 256, SMEM_BYTES>>>(q, k, v, rpe);
    fastmax_reduce<<<1024, 256>>>(out);
}

// round 12
// speedup vs baseline: 2.5089x; 1.3772x over previous
#include <cuda_runtime.h>
#include <cuda_bf16.h>
#include <cstdint>

// fastmax attention, B=1,H=8,N=2048,D=64, causal+RPE — tensor-core version.
// s(i,j) = q_i.k_j + QR2[i][i-j], QR2[i][d] = q_i.rpe[d+N-1] (precomputed GEMM)
// w = 1+s+s^2/2 (causal); out = (W V)/(W 1) via ones-column.
// All GEMMs: mma.sync m16n8k16 bf16, hi/lo split (3 MMAs, lo*lo dropped).

#define NSEQ 2048
#define DIM  64
#define NTILES 32
#define CHUNK 8
#define MAXSLOT 4
#define NH 8

typedef uint32_t u32;

__device__ float g_qr2[(size_t)NH * NSEQ * NSEQ];              // [h][i][d], 134MB
__device__ float g_pnum[NH * NTILES * MAXSLOT * 64 * 64];
__device__ float g_pden[NH * NTILES * MAXSLOT * 64];

__device__ __forceinline__ void mma(float* c, const u32* a, const u32* b) {
    asm volatile("mma.sync.aligned.m16n8k16.row.col.f32.bf16.bf16.f32 "
        "{%0,%1,%2,%3}, {%4,%5,%6,%7}, {%8,%9}, {%0,%1,%2,%3};"
        : "+f"(c[0]), "+f"(c[1]), "+f"(c[2]), "+f"(c[3])
        : "r"(a[0]), "r"(a[1]), "r"(a[2]), "r"(a[3]), "r"(b[0]), "r"(b[1]));
}
__device__ __forceinline__ u32 packbf(__nv_bfloat16 a, __nv_bfloat16 b) {
    return (u32)*reinterpret_cast<uint16_t*>(&a) |
           ((u32)*reinterpret_cast<uint16_t*>(&b) << 16);
}
__device__ __forceinline__ void split1(float x, __nv_bfloat16& h, __nv_bfloat16& l) {
    h = __float2bfloat16_rn(x);
    l = __float2bfloat16_rn(x - __bfloat162float(h));
}
__device__ __forceinline__ void split_pair(float x0, float x1, u32& hi, u32& lo) {
    __nv_bfloat16 h0, l0, h1, l1;
    split1(x0, h0, l0); split1(x1, h1, l1);
    hi = packbf(h0, h1); lo = packbf(l0, l1);
}
// A-frag (m16k16) from bf16 array, row stride 72
__device__ __forceinline__ void ldA(u32* a, const __nv_bfloat16* base, int row, int kc) {
    const __nv_bfloat16* p = base + row * 72 + kc;
    a[0] = *(const u32*)p;           a[1] = *(const u32*)(p + 8 * 72);
    a[2] = *(const u32*)(p + 8);     a[3] = *(const u32*)(p + 8 * 72 + 8);
}
// B-frag (k16n8) from col-major-equivalent [n][k] array, stride 72
__device__ __forceinline__ void ldB(u32* b, const __nv_bfloat16* base, int nr, int kc) {
    const __nv_bfloat16* p = base + nr * 72 + kc;
    b[0] = *(const u32*)p;           b[1] = *(const u32*)(p + 8);
}

// ============== Kernel 1: QR2 = Q * R^T, triangular 128x128 tiles ==============
#define QSM (4 * 128 * 72 * 2)
__global__ __launch_bounds__(256, 2)
void qr2_kernel(const float* __restrict__ q, const float* __restrict__ rpe)
{
    extern __shared__ char sm[];
    __nv_bfloat16* sQh = (__nv_bfloat16*)sm;
    __nv_bfloat16* sQl = sQh + 128 * 72;
    __nv_bfloat16* sRh = sQl + 128 * 72;
    __nv_bfloat16* sRl = sRh + 128 * 72;

    const int hd = blockIdx.y;
    int f = blockIdx.x, it = 0;
    while (f > it) { f -= (it + 1); it++; }
    const int dt = f;

    const int tid = threadIdx.x;
    #pragma unroll
    for (int e = 0; e < 32; e++) {
        int idx = tid + 256 * e;
        int r = idx >> 6, c = idx & 63;
        __nv_bfloat16 h, l;
        split1(q[((size_t)hd * NSEQ + 128 * it + r) * DIM + c], h, l);
        sQh[r * 72 + c] = h; sQl[r * 72 + c] = l;
        split1(rpe[(size_t)(NSEQ - 1 + 128 * dt + r) * DIM + c], h, l);
        sRh[r * 72 + c] = h; sRl[r * 72 + c] = l;
    }
    __syncthreads();

    const int wid = tid >> 5, lane = tid & 31;
    const int lg = lane >> 2, lq = lane & 3;
    const int mrow = wid * 16;

    u32 qh[4][4], ql[4][4];
    #pragma unroll
    for (int ks = 0; ks < 4; ks++) {
        ldA(qh[ks], sQh, mrow + lg, 16 * ks + 2 * lq);
        ldA(ql[ks], sQl, mrow + lg, 16 * ks + 2 * lq);
    }
    #pragma unroll
    for (int ng = 0; ng < 4; ng++) {
        float c[4][4];
        #pragma unroll
        for (int a = 0; a < 4; a++)
            #pragma unroll
            for (int b = 0; b < 4; b++) c[a][b] = 0.f;
        #pragma unroll
        for (int ks = 0; ks < 4; ks++)
            #pragma unroll
            for (int nl = 0; nl < 4; nl++) {
                u32 bh[2], bl[2];
                ldB(bh, sRh, 8 * (4 * ng + nl) + lg, 16 * ks + 2 * lq);
                ldB(bl, sRl, 8 * (4 * ng + nl) + lg, 16 * ks + 2 * lq);
                mma(c[nl], qh[ks], bh);
                mma(c[nl], ql[ks], bh);
                mma(c[nl], qh[ks], bl);
            }
        #pragma unroll
        for (int nl = 0; nl < 4; nl++) {
            size_t gi = (size_t)hd * NSEQ + 128 * it + mrow + lg;
            int gd = 128 * dt + 8 * (4 * ng + nl) + 2 * lq;
            *(float2*)(g_qr2 + gi * NSEQ + gd)       = make_float2(c[nl][0], c[nl][1]);
            *(float2*)(g_qr2 + (gi + 8) * NSEQ + gd) = make_float2(c[nl][2], c[nl][3]);
        }
    }
}

// ============== Kernel 2: attention partials (MMA mainloop) ==============
// smem: sQh 0, sQl 9216, sKh 18432, sKl 27648, sVth 36864, sVtl 47232,
//       sPar 57600 (64x68 f32) -> 75008.  sO overlays 18432 (64x76 f32).
#define PSM 75008
__global__ __launch_bounds__(256, 2)
void fastmax_partial(const float* __restrict__ q, const float* __restrict__ k,
                     const float* __restrict__ v)
{
    extern __shared__ char sm[];
    __nv_bfloat16* sQh  = (__nv_bfloat16*)sm;
    __nv_bfloat16* sQl  = sQh + 64 * 72;
    __nv_bfloat16* sKh  = (__nv_bfloat16*)(sm + 18432);
    __nv_bfloat16* sKl  = sKh + 64 * 72;
    __nv_bfloat16* sVth = (__nv_bfloat16*)(sm + 36864);   // [n][j], stride 72
    __nv_bfloat16* sVtl = (__nv_bfloat16*)(sm + 47232);
    float*         sPar = (float*)(sm + 57600);           // stride 68
    float*         sO   = (float*)(sm + 18432);           // stride 76, overlay

    const int hd = blockIdx.y;
    const int tid = threadIdx.x;
    const int wid = tid >> 5, lane = tid & 31;
    const int lg = lane >> 2, lq = lane & 3;
    const int wm = wid & 3, wn = wid >> 2;

    int rem = blockIdx.x, t = NTILES - 1;          // LPT: t descending
    for (;;) {
        int nb = (t + CHUNK) >> 3;
        if (rem < nb) break;
        rem -= nb; t--;
    }
    const int slot = rem;
    const int jt0 = slot * CHUNK, jt1 = min(jt0 + CHUNK, t + 1);
    const int i0 = t * 64;

    const float* gq = q + (size_t)hd * NSEQ * DIM;
    const float* gk = k + (size_t)hd * NSEQ * DIM;
    const float* gv = v + (size_t)hd * NSEQ * DIM;

    #pragma unroll
    for (int e = 0; e < 16; e++) {
        int idx = tid + 256 * e;
        int r = idx >> 6, c = idx & 63;
        __nv_bfloat16 h, l;
        split1(gq[(i0 + r) * DIM + c], h, l);
        sQh[r * 72 + c] = h; sQl[r * 72 + c] = l;
    }
    __syncthreads();

    u32 qh[4][4], ql[4][4];
    #pragma unroll
    for (int ks = 0; ks < 4; ks++) {
        ldA(qh[ks], sQh, 16 * wm + lg, 16 * ks + 2 * lq);
        ldA(ql[ks], sQl, 16 * wm + lg, 16 * ks + 2 * lq);
    }

    float oc[9][4];
    #pragma unroll
    for (int nt = 0; nt < 9; nt++)
        #pragma unroll
        for (int a = 0; a < 4; a++) oc[nt][a] = 0.f;

    for (int jt = jt0; jt < jt1; jt++) {
        const int j0 = jt * 64;
        __syncthreads();

        #pragma unroll
        for (int e = 0; e < 16; e++) {
            int idx = tid + 256 * e;
            int r = idx >> 6, c = idx & 63;
            __nv_bfloat16 h, l;
            split1(gk[(j0 + r) * DIM + c], h, l);
            sKh[r * 72 + c] = h; sKl[r * 72 + c] = l;
            split1(gv[(j0 + r) * DIM + c], h, l);
            sVth[c * 72 + r] = h; sVtl[c * 72 + r] = l;   // transposed
        }
        #pragma unroll
        for (int e = 0; e < 2; e++) {                      // ones col + pad
            int idx = tid + 256 * e;
            int n = 64 + (idx >> 6), j = idx & 63;
            sVth[n * 72 + j] = __float2bfloat16_rn(n == 64 ? 1.0f : 0.0f);
            sVtl[n * 72 + j] = __float2bfloat16_rn(0.0f);
        }
        {   // QR2 parallelogram: sPar[ir][c] = QR2[i0+ir][i0-j0+ir-63+c]
            const int d0 = i0 - j0;
            #pragma unroll
            for (int e = 0; e < 16; e++) {
                int idx = tid + 256 * e;
                int ir = idx >> 6, c = idx & 63;
                int d = d0 + ir - 63 + c;
                if (d < 0) d = 0;                          // masked region
                sPar[ir * 68 + c] = g_qr2[((size_t)hd * NSEQ + i0 + ir) * NSEQ + d];
            }
        }
        __syncthreads();

        // S = Q.K^T
        float sc[4][4];
        #pragma unroll
        for (int nt = 0; nt < 4; nt++)
            #pragma unroll
            for (int a = 0; a < 4; a++) sc[nt][a] = 0.f;
        #pragma unroll
        for (int ks = 0; ks < 4; ks++)
            #pragma unroll
            for (int nt = 0; nt < 4; nt++) {
                u32 bh[2], bl[2];
                ldB(bh, sKh, 32 * wn + 8 * nt + lg, 16 * ks + 2 * lq);
                ldB(bl, sKl, 32 * wn + 8 * nt + lg, 16 * ks + 2 * lq);
                mma(sc[nt], qh[ks], bh);
                mma(sc[nt], ql[ks], bh);
                mma(sc[nt], qh[ks], bl);
            }

        // epilogue: +QR2, weight, mask; build W A-frags in-register
        const bool diag = (j0 == i0);
        const int gi0 = i0 + 16 * wm + lg, gi1 = gi0 + 8;
        u32 wAh[2][4], wAl[2][4];
        #pragma unroll
        for (int nt = 0; nt < 4; nt++) {
            int jcl = 32 * wn + 8 * nt + 2 * lq;
            float2 p0 = *(const float2*)(sPar + (16 * wm + lg) * 68 + (62 - jcl));
            float2 p1 = *(const float2*)(sPar + (16 * wm + lg + 8) * 68 + (62 - jcl));
            float s0 = sc[nt][0] + p0.y;     // col jcl
            float s1 = sc[nt][1] + p0.x;     // col jcl+1
            float s2 = sc[nt][2] + p1.y;
            float s3 = sc[nt][3] + p1.x;
            float w0 = fmaf(0.5f * s0, s0, 1.0f + s0);
            float w1 = fmaf(0.5f * s1, s1, 1.0f + s1);
            float w2 = fmaf(0.5f * s2, s2, 1.0f + s2);
            float w3 = fmaf(0.5f * s3, s3, 1.0f + s3);
            if (diag) {
                int gj = j0 + jcl;
                if (gj     > gi0) w0 = 0.f;
                if (gj + 1 > gi0) w1 = 0.f;
                if (gj     > gi1) w2 = 0.f;
                if (gj + 1 > gi1) w3 = 0.f;
            }
            int kl = nt >> 1, hi = nt & 1;   // C(m16n8) == A(m16k16) layout reuse
            split_pair(w0, w1, wAh[kl][2 * hi], wAl[kl][2 * hi]);
            split_pair(w2, w3, wAh[kl][2 * hi + 1], wAl[kl][2 * hi + 1]);
        }

        // O += W.V' over this warp's 32-j slice
        #pragma unroll
        for (int kl = 0; kl < 2; kl++)
            #pragma unroll
            for (int nt = 0; nt < 9; nt++) {
                u32 bh[2], bl[2];
                ldB(bh, sVth, 8 * nt + lg, 32 * wn + 16 * kl + 2 * lq);
                ldB(bl, sVtl, 8 * nt + lg, 32 * wn + 16 * kl + 2 * lq);
                mma(oc[nt], wAh[kl], bh);
                mma(oc[nt], wAl[kl], bh);
                mma(oc[nt], wAh[kl], bl);
            }
    }

    // combine wn pair via smem; write partial slot
    __syncthreads();
    if (wn == 1) {
        #pragma unroll
        for (int nt = 0; nt < 9; nt++) {
            int col = 8 * nt + 2 * lq;
            *(float2*)(sO + (16 * wm + lg) * 76 + col)     = make_float2(oc[nt][0], oc[nt][1]);
            *(float2*)(sO + (16 * wm + lg + 8) * 76 + col) = make_float2(oc[nt][2], oc[nt][3]);
        }
    }
    __syncthreads();
    if (wn == 0) {
        const int sb = (hd * NTILES + t) * MAXSLOT + slot;
        float* pn = g_pnum + (size_t)sb * 4096;
        #pragma unroll
        for (int nt = 0; nt < 8; nt++) {
            int col = 8 * nt + 2 * lq;
            float2 q0 = *(const float2*)(sO + (16 * wm + lg) * 76 + col);
            float2 q1 = *(const float2*)(sO + (16 * wm + lg + 8) * 76 + col);
            *(float2*)(pn + (16 * wm + lg) * 64 + col) =
                make_float2(oc[nt][0] + q0.x, oc[nt][1] + q0.y);
            *(float2*)(pn + (16 * wm + lg + 8) * 64 + col) =
                make_float2(oc[nt][2] + q1.x, oc[nt][3] + q1.y);
        }
        if (lq == 0) {   // ones column (n=64) = denominator
            g_pden[sb * 64 + 16 * wm + lg]     = oc[8][0] + sO[(16 * wm + lg) * 76 + 64];
            g_pden[sb * 64 + 16 * wm + lg + 8] = oc[8][2] + sO[(16 * wm + lg + 8) * 76 + 64];
        }
    }
}

// ============== Kernel 3: reduce slots + normalize ==============
__global__ __launch_bounds__(256)
void fastmax_reduce(float* __restrict__ out)
{
    const int gi = blockIdx.x * 256 + threadIdx.x;
    const int rg = gi >> 4, c4 = gi & 15;
    const int hh = rg >> 11, i = rg & 2047;
    const int t = i >> 6, r = i & 63;
    const int nslots = (t + CHUNK) >> 3;

    const float4* pnum4 = reinterpret_cast<const float4*>(g_pnum);
    const size_t nb = ((size_t)(hh * NTILES + t) * MAXSLOT) * 1024 + r * 16 + c4;
    const size_t db = ((size_t)(hh * NTILES + t) * MAXSLOT) * 64 + r;

    float4 a = make_float4(0.f, 0.f, 0.f, 0.f);
    float den = 0.f;
    for (int s = 0; s < nslots; s++) {
        float4 p = pnum4[nb + (size_t)s * 1024];
        a.x += p.x; a.y += p.y; a.z += p.z; a.w += p.w;
        den += g_pden[db + (size_t)s * 64];
    }
    const float inv = 1.0f / den;
    reinterpret_cast<float4*>(out)[rg * 16 + c4] =
        make_float4(a.x * inv, a.y * inv, a.z * inv, a.w * inv);
}

extern "C" void kernel_launch(void* const* d_in, const int* in_sizes, int n_in,
                              void* d_out, int out_size)
{
    (void)in_sizes; (void)n_in; (void)out_size;
    const float* q   = (const float*)d_in[0];
    const float* k   = (const float*)d_in[1];
    const float* v   = (const float*)d_in[2];
    const float* rpe = (const float*)d_in[3];
    float* out = (float*)d_out;

    cudaFuncSetAttribute(qr2_kernel, cudaFuncAttributeMaxDynamicSharedMemorySize, QSM);
    cudaFuncSetAttribute(fastmax_partial, cudaFuncAttributeMaxDynamicSharedMemorySize, PSM);
    qr2_kernel<<<dim3(136, 8), 256, QSM>>>(q, rpe);
    fastmax_partial<<<dim3(80, 8), 256, PSM>>>(q, k, v);
    fastmax_reduce<<<1024, 256>>>(out);
}

// round 15
// speedup vs baseline: 3.0517x; 1.2163x over previous
#include <cuda_runtime.h>
#include <cuda_bf16.h>
#include <cstdint>

// fastmax attention, B=1,H=8,N=2048,D=64, causal+RPE — fused tensor-core version.
// s(i,j) = q_i.k_j + q_i.rpe[i-j+N-1];  w = 1+s+s^2/2 (causal)
// out = (W V)/(W 1) via ones-column.  RPE term computed IN-KERNEL as an
// incremental band GEMM QRb[ir][l] = q.rpe[rmin+l] into a circular smem buffer
// (64 new l-rows per j-tile).  All GEMMs: mma m16n8k16 bf16 hi/lo split (3 MMAs).

#define NSEQ 2048
#define DIM  64
#define NTILES 32
#define CHUNK 8
#define MAXSLOT 4
#define NH 8

typedef uint32_t u32;

__device__ float g_pnum[NH * NTILES * MAXSLOT * 64 * 64];
__device__ float g_pden[NH * NTILES * MAXSLOT * 64];

__device__ __forceinline__ void mma(float* c, const u32* a, const u32* b) {
    asm volatile("mma.sync.aligned.m16n8k16.row.col.f32.bf16.bf16.f32 "
        "{%0,%1,%2,%3}, {%4,%5,%6,%7}, {%8,%9}, {%0,%1,%2,%3};"
        : "+f"(c[0]), "+f"(c[1]), "+f"(c[2]), "+f"(c[3])
        : "r"(a[0]), "r"(a[1]), "r"(a[2]), "r"(a[3]), "r"(b[0]), "r"(b[1]));
}
__device__ __forceinline__ u32 packbf(__nv_bfloat16 a, __nv_bfloat16 b) {
    return (u32)*reinterpret_cast<uint16_t*>(&a) |
           ((u32)*reinterpret_cast<uint16_t*>(&b) << 16);
}
__device__ __forceinline__ void split1(float x, __nv_bfloat16& h, __nv_bfloat16& l) {
    h = __float2bfloat16_rn(x);
    l = __float2bfloat16_rn(x - __bfloat162float(h));
}
__device__ __forceinline__ void split_pair(float x0, float x1, u32& hi, u32& lo) {
    __nv_bfloat16 h0, l0, h1, l1;
    split1(x0, h0, l0); split1(x1, h1, l1);
    hi = packbf(h0, h1); lo = packbf(l0, l1);
}
__device__ __forceinline__ void ldA(u32* a, const __nv_bfloat16* base, int row, int kc) {
    const __nv_bfloat16* p = base + row * 72 + kc;
    a[0] = *(const u32*)p;           a[1] = *(const u32*)(p + 8 * 72);
    a[2] = *(const u32*)(p + 8);     a[3] = *(const u32*)(p + 8 * 72 + 8);
}
__device__ __forceinline__ void ldB(u32* b, const __nv_bfloat16* base, int nr, int kc) {
    const __nv_bfloat16* p = base + nr * 72 + kc;
    b[0] = *(const u32*)p;           b[1] = *(const u32*)(p + 8);
}

// smem: sQh 0, sQl 9216, sKh 18432, sKl 27648, sVth 36864, sVtl 47232,
//       sBh 57600, sBl 66816, sQR 76032 (64x132 f32) -> 109824.
//       sO overlays 18432 (64x76 f32) after mainloop.
#define PSM 109824
__global__ __launch_bounds__(256, 2)
void fastmax_partial(const float* __restrict__ q, const float* __restrict__ k,
                     const float* __restrict__ v, const float* __restrict__ rpe)
{
    extern __shared__ char sm[];
    __nv_bfloat16* sQh  = (__nv_bfloat16*)sm;
    __nv_bfloat16* sQl  = sQh + 64 * 72;
    __nv_bfloat16* sKh  = (__nv_bfloat16*)(sm + 18432);
    __nv_bfloat16* sKl  = sKh + 64 * 72;
    __nv_bfloat16* sVth = (__nv_bfloat16*)(sm + 36864);   // [n][j], stride 72
    __nv_bfloat16* sVtl = (__nv_bfloat16*)(sm + 47232);
    __nv_bfloat16* sBh  = (__nv_bfloat16*)(sm + 57600);   // band staging [m][d]
    __nv_bfloat16* sBl  = (__nv_bfloat16*)(sm + 66816);
    float*         sQR  = (float*)(sm + 76032);           // [ir][p] stride 132
    float*         sO   = (float*)(sm + 18432);           // overlay

    const int hd = blockIdx.y;
    const int tid = threadIdx.x;
    const int wid = tid >> 5, lane = tid & 31;
    const int lg = lane >> 2, lq = lane & 3;
    const int wm = wid & 3, wn = wid >> 2;

    int rem = blockIdx.x, t = NTILES - 1;          // LPT: t descending
    for (;;) {
        int nb = (t + CHUNK) >> 3;
        if (rem < nb) break;
        rem -= nb; t--;
    }
    const int slot = rem;
    const int jt0 = slot * CHUNK, jt1 = min(jt0 + CHUNK, t + 1);
    const int i0 = t * 64;

    const float* gq = q + (size_t)hd * NSEQ * DIM;
    const float* gk = k + (size_t)hd * NSEQ * DIM;
    const float* gv = v + (size_t)hd * NSEQ * DIM;

    #pragma unroll
    for (int e = 0; e < 16; e++) {
        int idx = tid + 256 * e;
        int r = idx >> 6, c = idx & 63;
        __nv_bfloat16 h, l;
        split1(gq[(i0 + r) * DIM + c], h, l);
        sQh[r * 72 + c] = h; sQl[r * 72 + c] = l;
    }
    __syncthreads();

    u32 qh[4][4], ql[4][4];
    #pragma unroll
    for (int ks = 0; ks < 4; ks++) {
        ldA(qh[ks], sQh, 16 * wm + lg, 16 * ks + 2 * lq);
        ldA(ql[ks], sQl, 16 * wm + lg, 16 * ks + 2 * lq);
    }

    float oc[9][4];
    #pragma unroll
    for (int nt = 0; nt < 9; nt++)
        #pragma unroll
        for (int a = 0; a < 4; a++) oc[nt][a] = 0.f;

    int roff = 0;

    for (int jt = jt0; jt < jt1; jt++) {
        const int j0 = jt * 64;
        const int rmin = i0 - j0 + NSEQ - 64;      // band base rel index (>=0)
        __syncthreads();

        // ---- K, V fills (bf16 split; V transposed with ones col) ----
        #pragma unroll
        for (int e = 0; e < 16; e++) {
            int idx = tid + 256 * e;
            int r = idx >> 6, c = idx & 63;
            __nv_bfloat16 h, l;
            split1(gk[(j0 + r) * DIM + c], h, l);
            sKh[r * 72 + c] = h; sKl[r * 72 + c] = l;
            split1(gv[(j0 + r) * DIM + c], h, l);
            sVth[c * 72 + r] = h; sVtl[c * 72 + r] = l;
        }
        #pragma unroll
        for (int e = 0; e < 2; e++) {
            int idx = tid + 256 * e;
            int n = 64 + (idx >> 6), j = idx & 63;
            sVth[n * 72 + j] = __float2bfloat16_rn(n == 64 ? 1.0f : 0.0f);
            sVtl[n * 72 + j] = __float2bfloat16_rn(0.0f);
        }
        // ---- band staging fill: rows m=0..63, rel = relbase + m ----
        const bool firstjt = (jt == jt0);
        int relbase = firstjt ? (rmin + 64) : rmin;
        if (!firstjt) roff ^= 64;
        #pragma unroll
        for (int e = 0; e < 16; e++) {
            int idx = tid + 256 * e;
            int r = idx >> 6, c = idx & 63;
            int rr = relbase + r;
            if (rr > 2 * NSEQ - 2) rr = 2 * NSEQ - 2;   // l=127 pad, never read
            __nv_bfloat16 h, l;
            split1(rpe[(size_t)rr * DIM + c], h, l);
            sBh[r * 72 + c] = h; sBl[r * 72 + c] = l;
        }
        __syncthreads();

        // ---- QRb incremental GEMM: out cols m -> sQR physical p = pbase+m ----
        {
            int pbase = firstjt ? 64 : roff;
            float qc[4][4];
            #pragma unroll
            for (int nt = 0; nt < 4; nt++)
                #pragma unroll
                for (int a = 0; a < 4; a++) qc[nt][a] = 0.f;
            #pragma unroll
            for (int ks = 0; ks < 4; ks++)
                #pragma unroll
                for (int nt = 0; nt < 4; nt++) {
                    u32 bh[2], bl[2];
                    ldB(bh, sBh, 32 * wn + 8 * nt + lg, 16 * ks + 2 * lq);
                    ldB(bl, sBl, 32 * wn + 8 * nt + lg, 16 * ks + 2 * lq);
                    mma(qc[nt], qh[ks], bh);
                    mma(qc[nt], ql[ks], bh);
                    mma(qc[nt], qh[ks], bl);
                }
            #pragma unroll
            for (int nt = 0; nt < 4; nt++) {
                int m0 = 32 * wn + 8 * nt + 2 * lq;
                int ir = 16 * wm + lg;
                *(float2*)(sQR + ir * 132 + pbase + m0)       = make_float2(qc[nt][0], qc[nt][1]);
                *(float2*)(sQR + (ir + 8) * 132 + pbase + m0) = make_float2(qc[nt][2], qc[nt][3]);
            }
        }
        if (firstjt) {   // second band pass: l = 0..63
            __syncthreads();
            #pragma unroll
            for (int e = 0; e < 16; e++) {
                int idx = tid + 256 * e;
                int r = idx >> 6, c = idx & 63;
                __nv_bfloat16 h, l;
                split1(rpe[(size_t)(rmin + r) * DIM + c], h, l);
                sBh[r * 72 + c] = h; sBl[r * 72 + c] = l;
            }
            __syncthreads();
            float qc[4][4];
            #pragma unroll
            for (int nt = 0; nt < 4; nt++)
                #pragma unroll
                for (int a = 0; a < 4; a++) qc[nt][a] = 0.f;
            #pragma unroll
            for (int ks = 0; ks < 4; ks++)
                #pragma unroll
                for (int nt = 0; nt < 4; nt++) {
                    u32 bh[2], bl[2];
                    ldB(bh, sBh, 32 * wn + 8 * nt + lg, 16 * ks + 2 * lq);
                    ldB(bl, sBl, 32 * wn + 8 * nt + lg, 16 * ks + 2 * lq);
                    mma(qc[nt], qh[ks], bh);
                    mma(qc[nt], ql[ks], bh);
                    mma(qc[nt], qh[ks], bl);
                }
            #pragma unroll
            for (int nt = 0; nt < 4; nt++) {
                int m0 = 32 * wn + 8 * nt + 2 * lq;
                int ir = 16 * wm + lg;
                *(float2*)(sQR + ir * 132 + m0)       = make_float2(qc[nt][0], qc[nt][1]);
                *(float2*)(sQR + (ir + 8) * 132 + m0) = make_float2(qc[nt][2], qc[nt][3]);
            }
        }

        // ---- S = Q.K^T ----
        float sc[4][4];
        #pragma unroll
        for (int nt = 0; nt < 4; nt++)
            #pragma unroll
            for (int a = 0; a < 4; a++) sc[nt][a] = 0.f;
        #pragma unroll
        for (int ks = 0; ks < 4; ks++)
            #pragma unroll
            for (int nt = 0; nt < 4; nt++) {
                u32 bh[2], bl[2];
                ldB(bh, sKh, 32 * wn + 8 * nt + lg, 16 * ks + 2 * lq);
                ldB(bl, sKl, 32 * wn + 8 * nt + lg, 16 * ks + 2 * lq);
                mma(sc[nt], qh[ks], bh);
                mma(sc[nt], ql[ks], bh);
                mma(sc[nt], qh[ks], bl);
            }
        __syncthreads();   // all warps' sQR stores visible for the gather

        // ---- epilogue: + QRb gather, weight, mask; W A-frags in-register ----
        const bool diag = (j0 == i0);
        const int ir0 = 16 * wm + lg;
        const int gi0 = i0 + ir0, gi1 = gi0 + 8;
        u32 wAh[2][4], wAl[2][4];
        #pragma unroll
        for (int nt = 0; nt < 4; nt++) {
            int jcl = 32 * wn + 8 * nt + 2 * lq;
            int lb = ir0 - jcl + 63;
            float s0 = sc[nt][0] + sQR[ir0 * 132 + ((lb + roff) & 127)];
            float s1 = sc[nt][1] + sQR[ir0 * 132 + ((lb - 1 + roff) & 127)];
            float s2 = sc[nt][2] + sQR[(ir0 + 8) * 132 + ((lb + 8 + roff) & 127)];
            float s3 = sc[nt][3] + sQR[(ir0 + 8) * 132 + ((lb + 7 + roff) & 127)];
            float w0 = fmaf(0.5f * s0, s0, 1.0f + s0);
            float w1 = fmaf(0.5f * s1, s1, 1.0f + s1);
            float w2 = fmaf(0.5f * s2, s2, 1.0f + s2);
            float w3 = fmaf(0.5f * s3, s3, 1.0f + s3);
            if (diag) {
                int gj = j0 + jcl;
                if (gj     > gi0) w0 = 0.f;
                if (gj + 1 > gi0) w1 = 0.f;
                if (gj     > gi1) w2 = 0.f;
                if (gj + 1 > gi1) w3 = 0.f;
            }
            int kl = nt >> 1, hi = nt & 1;
            split_pair(w0, w1, wAh[kl][2 * hi], wAl[kl][2 * hi]);
            split_pair(w2, w3, wAh[kl][2 * hi + 1], wAl[kl][2 * hi + 1]);
        }

        // ---- O += W.V' over this warp's 32-j slice ----
        #pragma unroll
        for (int kl = 0; kl < 2; kl++)
            #pragma unroll
            for (int nt = 0; nt < 9; nt++) {
                u32 bh[2], bl[2];
                ldB(bh, sVth, 8 * nt + lg, 32 * wn + 16 * kl + 2 * lq);
                ldB(bl, sVtl, 8 * nt + lg, 32 * wn + 16 * kl + 2 * lq);
                mma(oc[nt], wAh[kl], bh);
                mma(oc[nt], wAl[kl], bh);
                mma(oc[nt], wAh[kl], bl);
            }
    }

    // ---- combine wn pair via smem; write partial slot ----
    __syncthreads();
    if (wn == 1) {
        #pragma unroll
        for (int nt = 0; nt < 9; nt++) {
            int col = 8 * nt + 2 * lq;
            *(float2*)(sO + (16 * wm + lg) * 76 + col)     = make_float2(oc[nt][0], oc[nt][1]);
            *(float2*)(sO + (16 * wm + lg + 8) * 76 + col) = make_float2(oc[nt][2], oc[nt][3]);
        }
    }
    __syncthreads();
    if (wn == 0) {
        const int sb = (hd * NTILES + t) * MAXSLOT + slot;
        float* pn = g_pnum + (size_t)sb * 4096;
        #pragma unroll
        for (int nt = 0; nt < 8; nt++) {
            int col = 8 * nt + 2 * lq;
            float2 q0 = *(const float2*)(sO + (16 * wm + lg) * 76 + col);
            float2 q1 = *(const float2*)(sO + (16 * wm + lg + 8) * 76 + col);
            *(float2*)(pn + (16 * wm + lg) * 64 + col) =
                make_float2(oc[nt][0] + q0.x, oc[nt][1] + q0.y);
            *(float2*)(pn + (16 * wm + lg + 8) * 64 + col) =
                make_float2(oc[nt][2] + q1.x, oc[nt][3] + q1.y);
        }
        if (lq == 0) {
            g_pden[sb * 64 + 16 * wm + lg]     = oc[8][0] + sO[(16 * wm + lg) * 76 + 64];
            g_pden[sb * 64 + 16 * wm + lg + 8] = oc[8][2] + sO[(16 * wm + lg + 8) * 76 + 64];
        }
    }
}

__global__ __launch_bounds__(256)
void fastmax_reduce(float* __restrict__ out)
{
    const int gi = blockIdx.x * 256 + threadIdx.x;
    const int rg = gi >> 4, c4 = gi & 15;
    const int hh = rg >> 11, i = rg & 2047;
    const int t = i >> 6, r = i & 63;
    const int nslots = (t + CHUNK) >> 3;

    const float4* pnum4 = reinterpret_cast<const float4*>(g_pnum);
    const size_t nb = ((size_t)(hh * NTILES + t) * MAXSLOT) * 1024 + r * 16 + c4;
    const size_t db = ((size_t)(hh * NTILES + t) * MAXSLOT) * 64 + r;

    float4 a = make_float4(0.f, 0.f, 0.f, 0.f);
    float den = 0.f;
    for (int s = 0; s < nslots; s++) {
        float4 p = pnum4[nb + (size_t)s * 1024];
        a.x += p.x; a.y += p.y; a.z += p.z; a.w += p.w;
        den += g_pden[db + (size_t)s * 64];
    }
    const float inv = 1.0f / den;
    reinterpret_cast<float4*>(out)[rg * 16 + c4] =
        make_float4(a.x * inv, a.y * inv, a.z * inv, a.w * inv);
}

extern "C" void kernel_launch(void* const* d_in, const int* in_sizes, int n_in,
                              void* d_out, int out_size)
{
    (void)in_sizes; (void)n_in; (void)out_size;
    const float* q   = (const float*)d_in[0];
    const float* k   = (const float*)d_in[1];
    const float* v   = (const float*)d_in[2];
    const float* rpe = (const float*)d_in[3];
    float* out = (float*)d_out;

    cudaFuncSetAttribute(fastmax_partial, cudaFuncAttributeMaxDynamicSharedMemorySize, PSM);
    fastmax_partial<<<dim3(80, 8), 256, PSM>>>(q, k, v, rpe);
    fastmax_reduce<<<1024, 256>>>(out);
}